// round 12
// baseline (speedup 1.0000x reference)
#include <cuda_runtime.h>
#include <stdint.h>
#include <math.h>

#define L_LAYERS 10
#define NDIM 256
#define MDIM 64
#define BATCH 16384
#define BN_EPS 1e-5f

#define SZ_BM  (BATCH * MDIM)
#define SZ_BMN (1LL * BATCH * MDIM * NDIM)
#define SZ_LN  (L_LAYERS * NDIM)
#define SZ_LNN (1LL * L_LAYERS * NDIM * NDIM)
#define SZ_L   (L_LAYERS)
#define TOTAL  (BATCH * NDIM)

// ---------------- scratch ----------------------------------------------------
__device__ __align__(16) float g_ahy_r[TOTAL];
__device__ __align__(16) float g_ahy_i[TOTAL];
// ping-pong state buffers
__device__ __align__(16) float g_z_r[2][TOTAL];
__device__ __align__(16) float g_z_i[2][TOTAL];
__device__ __align__(16) float g_v_r[2][TOTAL];
__device__ __align__(16) float g_v_i[2][TOTAL];
__device__ float g_sum_r[NDIM];
__device__ float g_ssq_r[NDIM];
__device__ float g_sum_i[NDIM];
__device__ float g_ssq_i[NDIM];

__device__ __forceinline__ float sigmoidf_(float x) { return 1.f / (1.f + expf(-x)); }

// ---------------- A^H y ------------------------------------------------------
__global__ void ahy_kernel(const float* __restrict__ y_r,
                           const float* __restrict__ y_i,
                           const float* __restrict__ A_r,
                           const float* __restrict__ A_i) {
    int b = blockIdx.x;
    int n = threadIdx.x;
    __shared__ float sy_r[MDIM];
    __shared__ float sy_i[MDIM];
    if (n < MDIM) sy_r[n] = y_r[b * MDIM + n];
    else if (n < 2 * MDIM) sy_i[n - MDIM] = y_i[b * MDIM + (n - MDIM)];
    __syncthreads();

    const float* Ar = A_r + (size_t)b * MDIM * NDIM + n;
    const float* Ai = A_i + (size_t)b * MDIM * NDIM + n;
    float sr = 0.f, si = 0.f;
#pragma unroll 8
    for (int m = 0; m < MDIM; m++) {
        float ar = Ar[(size_t)m * NDIM];
        float ai = Ai[(size_t)m * NDIM];
        float yr = sy_r[m], yi = sy_i[m];
        sr += ar * yr + ai * yi;
        si += ar * yi - ai * yr;
    }
    g_ahy_r[(size_t)b * NDIM + n] = sr;
    g_ahy_i[(size_t)b * NDIM + n] = si;
}

// ---------------- BatchNorm stats -------------------------------------------
__global__ void zero_stats_kernel() {
    int n = threadIdx.x;
    if (n < NDIM) {
        g_sum_r[n] = 0.f; g_ssq_r[n] = 0.f;
        g_sum_i[n] = 0.f; g_ssq_i[n] = 0.f;
    }
}

__global__ void bn_reduce_kernel() {
    int n = threadIdx.x;
    int r0 = blockIdx.x * 128;
    float sr = 0.f, qr = 0.f, si = 0.f, qi = 0.f;
#pragma unroll 4
    for (int r = 0; r < 128; r++) {
        float vr = g_ahy_r[(size_t)(r0 + r) * NDIM + n];
        float vi = g_ahy_i[(size_t)(r0 + r) * NDIM + n];
        sr += vr; qr += vr * vr;
        si += vi; qi += vi * vi;
    }
    atomicAdd(&g_sum_r[n], sr);
    atomicAdd(&g_ssq_r[n], qr);
    atomicAdd(&g_sum_i[n], si);
    atomicAdd(&g_ssq_i[n], qi);
}

// BN apply + fused analytic layer 0 (z=v=0). Writes state buffer 0.
__global__ void bn_apply_layer0_kernel(const float* __restrict__ wdr0,
                                       const float* __restrict__ wdi0,
                                       const float* __restrict__ reta,
                                       const float* __restrict__ br0,
                                       const float* __restrict__ ubr0,
                                       const float* __restrict__ bi0,
                                       const float* __restrict__ ubi0) {
    int idx = blockIdx.x * blockDim.x + threadIdx.x;
    if (idx >= TOTAL) return;
    int n = idx & (NDIM - 1);
    const float invB = 1.f / (float)BATCH;
    float mr = g_sum_r[n] * invB;
    float vr = g_ssq_r[n] * invB - mr * mr;
    float irr = rsqrtf(vr + BN_EPS);
    float mi = g_sum_i[n] * invB;
    float vi2 = g_ssq_i[n] * invB - mi * mi;
    float iri = rsqrtf(vi2 + BN_EPS);
    float ahr = (g_ahy_r[idx] - mr) * irr;
    float ahi = (g_ahy_i[idx] - mi) * iri;
    g_ahy_r[idx] = ahr;
    g_ahy_i[idx] = ahi;

    float re = __ldg(reta);
    float eta = (re > 20.f) ? re : log1pf(expf(re));
    float dr = __ldg(&wdr0[n]) + eta;
    float di = __ldg(&wdi0[n]);
    float inv = 1.f / (dr * dr + di * di);
    float xr = (ahr * dr + ahi * di) * inv;
    float xi = (ahi * dr - ahr * di) * inv;
    float gr = sigmoidf_(__ldg(&br0[n]) + __ldg(&ubr0[n]));
    float gi = sigmoidf_(__ldg(&bi0[n]) + __ldg(&ubi0[n]));
    float znr = gr * xr - gi * xi;
    float zni = gr * xi + gi * xr;
    g_z_r[0][idx] = znr; g_z_i[0][idx] = zni;
    g_v_r[0][idx] = xr - znr;
    g_v_i[0][idx] = xi - zni;
}

// ---------------- fused layer: both-parity gate GEMM + state update ---------
// CTA: 128 rows x 128 cols, both parities. 256 threads = 8 warps.
// Warps 0-3: real parity (2x2 of 64x64). Warps 4-7: imag parity.
// tf32 mma.m16n8k8, ldmatrix fragment loads, cp.async double buffer.
#define GK 16
#define GSTRIDE 20
#define GNIT 32
#define GEPS 130   // G-exchange smem stride

// dynamic smem float offsets
#define SM_A(p, b) (((p) * 2 + (b)) * 128 * GSTRIDE)
#define SM_B(p, b) (4 * 128 * GSTRIDE + ((p) * 2 + (b)) * 128 * GSTRIDE)
#define SM_G(p)    (8 * 128 * GSTRIDE + (p) * 64 * GEPS)
#define SMEM_FLOATS (8 * 128 * GSTRIDE + 2 * 64 * GEPS)

__device__ __forceinline__ unsigned int f2tf32(float f) {
    unsigned int u;
    asm("cvt.rna.tf32.f32 %0, %1;" : "=r"(u) : "f"(f));
    return u;
}
__device__ __forceinline__ void cp16(unsigned int dst, const float* src) {
    asm volatile("cp.async.cg.shared.global [%0], [%1], 16;" :: "r"(dst), "l"(src));
}
__device__ __forceinline__ void cp_commit() {
    asm volatile("cp.async.commit_group;" ::: "memory");
}
template <int N>
__device__ __forceinline__ void cp_wait() {
    asm volatile("cp.async.wait_group %0;" :: "n"(N) : "memory");
}
__device__ __forceinline__ void ldsm4(unsigned int& r0, unsigned int& r1,
                                      unsigned int& r2, unsigned int& r3,
                                      unsigned int addr) {
    asm volatile("ldmatrix.sync.aligned.m8n8.x4.shared.b16 {%0,%1,%2,%3}, [%4];"
                 : "=r"(r0), "=r"(r1), "=r"(r2), "=r"(r3) : "r"(addr));
}
__device__ __forceinline__ void mma_tf32(float* c, const unsigned int* a,
                                         const unsigned int* b) {
    asm volatile(
        "mma.sync.aligned.m16n8k8.row.col.f32.tf32.tf32.f32 "
        "{%0,%1,%2,%3},{%4,%5,%6,%7},{%8,%9},{%0,%1,%2,%3};"
        : "+f"(c[0]), "+f"(c[1]), "+f"(c[2]), "+f"(c[3])
        : "r"(a[0]), "r"(a[1]), "r"(a[2]), "r"(a[3]), "r"(b[0]), "r"(b[1]));
}

__global__ __launch_bounds__(256, 1)
void fused_layer_kernel(const float* __restrict__ Wr, const float* __restrict__ Ur,
                        const float* __restrict__ br, const float* __restrict__ ubr,
                        const float* __restrict__ Wi, const float* __restrict__ Ui,
                        const float* __restrict__ bi, const float* __restrict__ ubi,
                        const float* __restrict__ wdr, const float* __restrict__ wdi,
                        const float* __restrict__ reta_l,
                        int rb, int wb, int last,
                        float* __restrict__ out, long long max_floats,
                        const float* thr, const float* alpha, int use_ptrs) {
    extern __shared__ float sm[];

    const int tid  = threadIdx.x;
    const int col0 = blockIdx.x * 128;
    const int row0 = blockIdx.y * 128;
    const int wid  = tid >> 5, lane = tid & 31;
    const int par  = wid >> 2;            // 0 = real, 1 = imag
    const int wq   = wid & 3;
    const int wm   = wq >> 1, wn = wq & 1;  // 2x2 warps of 64x64 within parity
    const int grp  = lane >> 2, tig = lane & 3;

    // ldmatrix lane selectors
    const int rselA = (lane & 7) + ((lane >> 3) & 1) * 8;
    const int kselA = (lane >> 4) * 4;
    const int cselB = (lane & 7) + (lane >> 4) * 8;
    const int kselB = ((lane >> 3) & 1) * 4;

    // loader indexing: per tile, thread handles 2 float4 chunks
    const int lrow = tid >> 2;        // 0..63
    const int lk4  = (tid & 3) * 4;   // 0,4,8,12

    const float* Zr = g_z_r[rb]; const float* Zi = g_z_i[rb];
    const float* Vr = g_v_r[rb]; const float* Vi = g_v_i[rb];

    float acc[4][8][4];
#pragma unroll
    for (int a = 0; a < 4; a++)
#pragma unroll
        for (int b = 0; b < 8; b++)
#pragma unroll
            for (int c = 0; c < 4; c++) acc[a][b][c] = 0.f;

    unsigned int smb = (unsigned int)__cvta_generic_to_shared(sm);

    auto load_tiles = [&](int it, int buf) {
        int kg = it * GK;
        int kk = kg & 255;
        const float* a0 = (kg < 256) ? Zr : Vr;   // parity 0 A
        const float* a1 = (kg < 256) ? Zi : Vi;   // parity 1 A
        const float* b0 = (kg < 256) ? Wr : Ur;
        const float* b1 = (kg < 256) ? Wi : Ui;
#pragma unroll
        for (int j = 0; j < 2; j++) {
            int r = lrow + j * 64;
            unsigned int so = (unsigned int)((r * GSTRIDE + lk4) * 4);
            cp16(smb + SM_A(0, buf) * 4 + so, a0 + (size_t)(row0 + r) * NDIM + kk + lk4);
            cp16(smb + SM_A(1, buf) * 4 + so, a1 + (size_t)(row0 + r) * NDIM + kk + lk4);
            cp16(smb + SM_B(0, buf) * 4 + so, b0 + (size_t)(col0 + r) * NDIM + kk + lk4);
            cp16(smb + SM_B(1, buf) * 4 + so, b1 + (size_t)(col0 + r) * NDIM + kk + lk4);
        }
        cp_commit();
    };

    load_tiles(0, 0);

    for (int i = 0; i < GNIT; i++) {
        if (i + 1 < GNIT) {
            load_tiles(i + 1, (i + 1) & 1);
            cp_wait<1>();
        } else {
            cp_wait<0>();
        }
        __syncthreads();

        unsigned int aB = smb + SM_A(par, i & 1) * 4;
        unsigned int bB = smb + SM_B(par, i & 1) * 4;
#pragma unroll
        for (int ks = 0; ks < 2; ks++) {
            int kb = ks * 8;
            unsigned int af[4][4], bf[8][2];
#pragma unroll
            for (int mt = 0; mt < 4; mt++) {
                unsigned int ad = aB + (unsigned int)(((wm * 64 + mt * 16 + rselA) * GSTRIDE
                                                      + kb + kselA) * 4);
                ldsm4(af[mt][0], af[mt][1], af[mt][2], af[mt][3], ad);
#pragma unroll
                for (int q = 0; q < 4; q++) af[mt][q] = f2tf32(__uint_as_float(af[mt][q]));
            }
#pragma unroll
            for (int np = 0; np < 4; np++) {
                unsigned int bd = bB + (unsigned int)(((wn * 64 + np * 16 + cselB) * GSTRIDE
                                                      + kb + kselB) * 4);
                ldsm4(bf[2 * np][0], bf[2 * np][1], bf[2 * np + 1][0], bf[2 * np + 1][1], bd);
                bf[2 * np][0]     = f2tf32(__uint_as_float(bf[2 * np][0]));
                bf[2 * np][1]     = f2tf32(__uint_as_float(bf[2 * np][1]));
                bf[2 * np + 1][0] = f2tf32(__uint_as_float(bf[2 * np + 1][0]));
                bf[2 * np + 1][1] = f2tf32(__uint_as_float(bf[2 * np + 1][1]));
            }
#pragma unroll
            for (int mt = 0; mt < 4; mt++)
#pragma unroll
                for (int nt = 0; nt < 8; nt++)
                    mma_tf32(acc[mt][nt], af[mt], bf[nt]);
        }
        __syncthreads();
    }

    // ---------------- fused epilogue: G exchange + state update -------------
    const float* B1 = par ? bi : br;
    const float* B2 = par ? ubi : ubr;
    float* sG = sm + 8 * 128 * GSTRIDE;   // [2][64][GEPS]

    float re = __ldg(reta_l);
    float eta = (re > 20.f) ? re : log1pf(expf(re));
    const int cme = tid & 127;            // this thread's column in update phase
    const int cg_u = col0 + cme;
    float dr_u = __ldg(&wdr[cg_u]) + eta;
    float di_u = __ldg(&wdi[cg_u]);
    float inv_u = 1.f / (dr_u * dr_u + di_u * di_u);
    float t_m = use_ptrs ? __ldg(thr) : 0.1f;
    float a_m = use_ptrs ? __ldg(alpha) : 2.0f;

    float* ZWr = g_z_r[wb]; float* ZWi = g_z_i[wb];
    float* VWr = g_v_r[wb]; float* VWi = g_v_i[wb];

#pragma unroll
    for (int half = 0; half < 2; half++) {
        if (wm == half) {
            float* sGp = sG + par * 64 * GEPS;
#pragma unroll
            for (int nt = 0; nt < 8; nt++) {
                int cl = wn * 64 + nt * 8 + tig * 2;
                int cg = col0 + cl;
                float bv0 = __ldg(&B1[cg]) + __ldg(&B2[cg]);
                float bv1 = __ldg(&B1[cg + 1]) + __ldg(&B2[cg + 1]);
#pragma unroll
                for (int mt = 0; mt < 4; mt++) {
                    int rl = mt * 16 + grp;
                    sGp[rl * GEPS + cl]           = sigmoidf_(acc[mt][nt][0] + bv0);
                    sGp[rl * GEPS + cl + 1]       = sigmoidf_(acc[mt][nt][1] + bv1);
                    sGp[(rl + 8) * GEPS + cl]     = sigmoidf_(acc[mt][nt][2] + bv0);
                    sGp[(rl + 8) * GEPS + cl + 1] = sigmoidf_(acc[mt][nt][3] + bv1);
                }
            }
        }
        __syncthreads();

        // all 256 threads update this 64x128 half-tile
        int rl0 = tid >> 7;  // 0 or 1
#pragma unroll 4
        for (int k = 0; k < 32; k++) {
            int rl = rl0 + 2 * k;
            int r = row0 + half * 64 + rl;
            int idx = r * NDIM + cg_u;

            float gr = sG[rl * GEPS + cme];
            float gi = sG[64 * GEPS + rl * GEPS + cme];

            float ahr = g_ahy_r[idx], ahi = g_ahy_i[idx];
            float zr = Zr[idx], zi = Zi[idx];
            float vr = Vr[idx], vi = Vi[idx];

            float nr = ahr + eta * (zr - vr);
            float ni = ahi + eta * (zi - vi);
            float xr = (nr * dr_u + ni * di_u) * inv_u;
            float xi = (ni * dr_u - nr * di_u) * inv_u;
            float ur = xr + vr, ui = xi + vi;

            float znr = gr * ur - gi * ui + (1.f - gr) * zr + gi * zi;
            float zni = gr * ui + gi * ur + (1.f - gr) * zi - gi * zr;

            if (last) {
                float amp = sqrtf(znr * znr + zni * zni);
                float m = 1.f / (1.f + expf(-a_m * (amp - t_m)));
                if (idx < max_floats) out[idx] = znr * m;
                long long o = (long long)idx + TOTAL;
                if (o < max_floats) out[o] = zni * m;
            } else {
                ZWr[idx] = znr; ZWi[idx] = zni;
                VWr[idx] = vr + xr - znr;
                VWi[idx] = vi + xi - zni;
            }
        }
        __syncthreads();
    }
}

// ---------------- launch ----------------------------------------------------
extern "C" void kernel_launch(void* const* d_in, const int* in_sizes, int n_in,
                              void* d_out, int out_size) {
    static const long long sig[17] = {SZ_BM, SZ_BM, SZ_BMN, SZ_BMN, SZ_LN, SZ_LN, SZ_L,
                                      SZ_LNN, SZ_LN, SZ_LNN, SZ_LN, SZ_LNN, SZ_LN,
                                      SZ_LNN, SZ_LN, 1, 1};
    static const long long srt[17] = {SZ_BMN, SZ_BMN, SZ_LN, SZ_LNN, SZ_LN, SZ_LNN,
                                      SZ_LN, SZ_LNN, SZ_LN, SZ_LNN, 1, SZ_L, 1,
                                      SZ_LN, SZ_LN, SZ_BM, SZ_BM};

    int map[17];
    int have_scalars = 0;
    int matched = 0;

    if (n_in == 17 || n_in == 15) {
        int ok = 1;
        for (int i = 0; i < n_in; i++)
            if ((long long)in_sizes[i] != sig[i]) { ok = 0; break; }
        if (ok) {
            for (int i = 0; i < 17; i++) map[i] = i;
            have_scalars = (n_in == 17);
            matched = 1;
        }
    }
    if (!matched && n_in == 17) {
        int ok = 1;
        for (int i = 0; i < 17; i++)
            if ((long long)in_sizes[i] != srt[i]) { ok = 0; break; }
        if (ok) {
            map[3] = 0;  map[2] = 1;  map[14] = 2; map[13] = 3; map[10] = 4;
            map[9] = 5;  map[12] = 6; map[11] = 7; map[8] = 8;  map[7] = 9;
            map[16] = 10; map[6] = 11; map[15] = 12; map[5] = 13; map[4] = 14;
            map[1] = 15; map[0] = 16;
            have_scalars = 1;
            matched = 2;
        }
    }
    if (!matched && n_in == 17) {
        int ok = 1;
        for (int i = 0; i < 17; i++)
            if ((long long)in_sizes[i] != sig[16 - i]) { ok = 0; break; }
        if (ok) {
            for (int i = 0; i < 17; i++) map[i] = 16 - i;
            have_scalars = 1;
            matched = 3;
        }
    }

    if (!matched) return;

    const float* y_r   = (const float*)d_in[map[0]];
    const float* y_i   = (const float*)d_in[map[1]];
    const float* A_r   = (const float*)d_in[map[2]];
    const float* A_i   = (const float*)d_in[map[3]];
    const float* wdr   = (const float*)d_in[map[4]];
    const float* wdi   = (const float*)d_in[map[5]];
    const float* reta  = (const float*)d_in[map[6]];
    const float* Wr    = (const float*)d_in[map[7]];
    const float* br    = (const float*)d_in[map[8]];
    const float* Ur    = (const float*)d_in[map[9]];
    const float* ubr   = (const float*)d_in[map[10]];
    const float* Wi    = (const float*)d_in[map[11]];
    const float* bi    = (const float*)d_in[map[12]];
    const float* Ui    = (const float*)d_in[map[13]];
    const float* ubi   = (const float*)d_in[map[14]];
    const float* thr   = have_scalars ? (const float*)d_in[map[15]] : (const float*)0;
    const float* alpha = have_scalars ? (const float*)d_in[map[16]] : (const float*)0;

    const int EW_BLOCKS = TOTAL / 256;
    const int SMEM_BYTES = SMEM_FLOATS * 4;

    cudaFuncSetAttribute(fused_layer_kernel,
                         cudaFuncAttributeMaxDynamicSharedMemorySize, SMEM_BYTES);

    zero_stats_kernel<<<1, 256>>>();
    ahy_kernel<<<BATCH, 256>>>(y_r, y_i, A_r, A_i);
    bn_reduce_kernel<<<BATCH / 128, 256>>>();
    bn_apply_layer0_kernel<<<EW_BLOCKS, 256>>>(wdr, wdi, reta, br, ubr, bi, ubi);

    for (int l = 1; l < L_LAYERS; l++) {
        size_t wo = (size_t)l * NDIM * NDIM;
        size_t bo = (size_t)l * NDIM;
        int rb = (l + 1) & 1;   // read buffer  (layer1 reads buf0)
        int wb = l & 1;         // write buffer
        int last = (l == L_LAYERS - 1);
        dim3 grid(NDIM / 128, BATCH / 128);
        fused_layer_kernel<<<grid, 256, SMEM_BYTES>>>(
            Wr + wo, Ur + wo, br + bo, ubr + bo,
            Wi + wo, Ui + wo, bi + bo, ubi + bo,
            wdr + bo, wdi + bo, reta + l,
            rb, wb, last,
            (float*)d_out, (long long)out_size, thr, alpha, have_scalars);
    }
}

// round 13
// speedup vs baseline: 1.4857x; 1.4857x over previous
#include <cuda_runtime.h>
#include <stdint.h>
#include <math.h>

#define L_LAYERS 10
#define NDIM 256
#define MDIM 64
#define BATCH 16384
#define BN_EPS 1e-5f

#define SZ_BM  (BATCH * MDIM)
#define SZ_BMN (1LL * BATCH * MDIM * NDIM)
#define SZ_LN  (L_LAYERS * NDIM)
#define SZ_LNN (1LL * L_LAYERS * NDIM * NDIM)
#define SZ_L   (L_LAYERS)
#define TOTAL  (BATCH * NDIM)

// ---------------- scratch ----------------------------------------------------
__device__ __align__(16) float g_ahy_r[TOTAL];
__device__ __align__(16) float g_ahy_i[TOTAL];
__device__ __align__(16) float g_z_r[TOTAL];
__device__ __align__(16) float g_z_i[TOTAL];
__device__ __align__(16) float g_v_r[TOTAL];
__device__ __align__(16) float g_v_i[TOTAL];
__device__ __align__(16) float g_g_r[TOTAL];
__device__ __align__(16) float g_g_i[TOTAL];
__device__ float g_sum_r[NDIM];
__device__ float g_ssq_r[NDIM];
__device__ float g_sum_i[NDIM];
__device__ float g_ssq_i[NDIM];

__device__ __forceinline__ float sigmoidf_(float x) { return 1.f / (1.f + expf(-x)); }

// ---------------- A^H y ------------------------------------------------------
__global__ void ahy_kernel(const float* __restrict__ y_r,
                           const float* __restrict__ y_i,
                           const float* __restrict__ A_r,
                           const float* __restrict__ A_i) {
    int b = blockIdx.x;
    int n = threadIdx.x;
    __shared__ float sy_r[MDIM];
    __shared__ float sy_i[MDIM];
    if (n < MDIM) sy_r[n] = y_r[b * MDIM + n];
    else if (n < 2 * MDIM) sy_i[n - MDIM] = y_i[b * MDIM + (n - MDIM)];
    __syncthreads();

    const float* Ar = A_r + (size_t)b * MDIM * NDIM + n;
    const float* Ai = A_i + (size_t)b * MDIM * NDIM + n;
    float sr = 0.f, si = 0.f;
#pragma unroll 8
    for (int m = 0; m < MDIM; m++) {
        float ar = Ar[(size_t)m * NDIM];
        float ai = Ai[(size_t)m * NDIM];
        float yr = sy_r[m], yi = sy_i[m];
        sr += ar * yr + ai * yi;
        si += ar * yi - ai * yr;
    }
    g_ahy_r[(size_t)b * NDIM + n] = sr;
    g_ahy_i[(size_t)b * NDIM + n] = si;
}

// ---------------- BatchNorm stats -------------------------------------------
__global__ void zero_stats_kernel() {
    int n = threadIdx.x;
    if (n < NDIM) {
        g_sum_r[n] = 0.f; g_ssq_r[n] = 0.f;
        g_sum_i[n] = 0.f; g_ssq_i[n] = 0.f;
    }
}

__global__ void bn_reduce_kernel() {
    int n = threadIdx.x;
    int r0 = blockIdx.x * 128;
    float sr = 0.f, qr = 0.f, si = 0.f, qi = 0.f;
#pragma unroll 4
    for (int r = 0; r < 128; r++) {
        float vr = g_ahy_r[(size_t)(r0 + r) * NDIM + n];
        float vi = g_ahy_i[(size_t)(r0 + r) * NDIM + n];
        sr += vr; qr += vr * vr;
        si += vi; qi += vi * vi;
    }
    atomicAdd(&g_sum_r[n], sr);
    atomicAdd(&g_ssq_r[n], qr);
    atomicAdd(&g_sum_i[n], si);
    atomicAdd(&g_ssq_i[n], qi);
}

// BN apply + fused analytic layer 0 (z=v=0)
__global__ void bn_apply_layer0_kernel(const float* __restrict__ wdr0,
                                       const float* __restrict__ wdi0,
                                       const float* __restrict__ reta,
                                       const float* __restrict__ br0,
                                       const float* __restrict__ ubr0,
                                       const float* __restrict__ bi0,
                                       const float* __restrict__ ubi0) {
    int idx = blockIdx.x * blockDim.x + threadIdx.x;
    if (idx >= TOTAL) return;
    int n = idx & (NDIM - 1);
    const float invB = 1.f / (float)BATCH;
    float mr = g_sum_r[n] * invB;
    float vr = g_ssq_r[n] * invB - mr * mr;
    float irr = rsqrtf(vr + BN_EPS);
    float mi = g_sum_i[n] * invB;
    float vi2 = g_ssq_i[n] * invB - mi * mi;
    float iri = rsqrtf(vi2 + BN_EPS);
    float ahr = (g_ahy_r[idx] - mr) * irr;
    float ahi = (g_ahy_i[idx] - mi) * iri;
    g_ahy_r[idx] = ahr;
    g_ahy_i[idx] = ahi;

    float re = __ldg(reta);
    float eta = (re > 20.f) ? re : log1pf(expf(re));
    float dr = __ldg(&wdr0[n]) + eta;
    float di = __ldg(&wdi0[n]);
    float inv = 1.f / (dr * dr + di * di);
    float xr = (ahr * dr + ahi * di) * inv;
    float xi = (ahi * dr - ahr * di) * inv;
    float gr = sigmoidf_(__ldg(&br0[n]) + __ldg(&ubr0[n]));
    float gi = sigmoidf_(__ldg(&bi0[n]) + __ldg(&ubi0[n]));
    float znr = gr * xr - gi * xi;
    float zni = gr * xi + gi * xr;
    g_z_r[idx] = znr; g_z_i[idx] = zni;
    g_v_r[idx] = xr - znr;
    g_v_i[idx] = xi - zni;
}

// ---------------- tf32 tensor-core gate GEMM (ldmatrix fragments) -----------
// G = sigmoid([Z|V] @ [W|U]^T + bW + bU), effective K = 512.
// CTA tile 128x128, BK=16, 4 warps of 64x64, mma.m16n8k8.tf32, cp.async 2-stage.
#define GK 16
#define GSTRIDE 20
#define GNIT 32

__device__ __forceinline__ unsigned int f2tf32(float f) {
    unsigned int u;
    asm("cvt.rna.tf32.f32 %0, %1;" : "=r"(u) : "f"(f));
    return u;
}
__device__ __forceinline__ void cp16(unsigned int dst, const float* src) {
    asm volatile("cp.async.cg.shared.global [%0], [%1], 16;" :: "r"(dst), "l"(src));
}
__device__ __forceinline__ void cp_commit() {
    asm volatile("cp.async.commit_group;" ::: "memory");
}
template <int N>
__device__ __forceinline__ void cp_wait() {
    asm volatile("cp.async.wait_group %0;" :: "n"(N) : "memory");
}
__device__ __forceinline__ void ldsm4(unsigned int& r0, unsigned int& r1,
                                      unsigned int& r2, unsigned int& r3,
                                      unsigned int addr) {
    asm volatile("ldmatrix.sync.aligned.m8n8.x4.shared.b16 {%0,%1,%2,%3}, [%4];"
                 : "=r"(r0), "=r"(r1), "=r"(r2), "=r"(r3) : "r"(addr));
}
__device__ __forceinline__ void mma_tf32(float* c, const unsigned int* a,
                                         const unsigned int* b) {
    asm volatile(
        "mma.sync.aligned.m16n8k8.row.col.f32.tf32.tf32.f32 "
        "{%0,%1,%2,%3},{%4,%5,%6,%7},{%8,%9},{%0,%1,%2,%3};"
        : "+f"(c[0]), "+f"(c[1]), "+f"(c[2]), "+f"(c[3])
        : "r"(a[0]), "r"(a[1]), "r"(a[2]), "r"(a[3]), "r"(b[0]), "r"(b[1]));
}

__global__ __launch_bounds__(128, 2)
void gate_gemm_tf32(const float* __restrict__ Wr, const float* __restrict__ Ur,
                    const float* __restrict__ br, const float* __restrict__ ubr,
                    const float* __restrict__ Wi, const float* __restrict__ Ui,
                    const float* __restrict__ bi, const float* __restrict__ ubi) {
    const float* Z  = blockIdx.z ? g_z_i : g_z_r;
    const float* V  = blockIdx.z ? g_v_i : g_v_r;
    const float* W  = blockIdx.z ? Wi : Wr;
    const float* U  = blockIdx.z ? Ui : Ur;
    const float* B1 = blockIdx.z ? bi : br;
    const float* B2 = blockIdx.z ? ubi : ubr;
    float* G        = blockIdx.z ? g_g_i : g_g_r;

    __shared__ float As[2][128 * GSTRIDE];
    __shared__ float Bs[2][128 * GSTRIDE];

    const int tid  = threadIdx.x;
    const int row0 = blockIdx.y * 128;
    const int col0 = blockIdx.x * 128;
    const int wid  = tid >> 5, lane = tid & 31;
    const int wm = wid >> 1, wn = wid & 1;   // 2x2 warps, each 64x64
    const int grp = lane >> 2, tig = lane & 3;

    // ldmatrix lane address selectors (validated in round 12)
    const int rselA = (lane & 7) + ((lane >> 3) & 1) * 8;
    const int kselA = (lane >> 4) * 4;
    const int cselB = (lane & 7) + (lane >> 4) * 8;
    const int kselB = ((lane >> 3) & 1) * 4;

    const int lrow = tid >> 2;       // 0..31
    const int lk4  = (tid & 3) * 4;  // 0,4,8,12

    float acc[4][8][4];
#pragma unroll
    for (int a = 0; a < 4; a++)
#pragma unroll
        for (int b = 0; b < 8; b++)
#pragma unroll
            for (int c = 0; c < 4; c++) acc[a][b][c] = 0.f;

    unsigned int asb = (unsigned int)__cvta_generic_to_shared(&As[0][0]);
    unsigned int bsb = (unsigned int)__cvta_generic_to_shared(&Bs[0][0]);

    auto load_tile = [&](int it, int buf) {
        int kg = it * GK;
        const float* a_src = (kg < 256) ? Z : V;
        const float* b_src = (kg < 256) ? W : U;
        int kk = kg & 255;
        unsigned int ab = asb + (unsigned int)(buf * 128 * GSTRIDE) * 4u;
        unsigned int bb = bsb + (unsigned int)(buf * 128 * GSTRIDE) * 4u;
#pragma unroll
        for (int j = 0; j < 4; j++) {
            int r = lrow + j * 32;
            cp16(ab + (unsigned int)(r * GSTRIDE + lk4) * 4u,
                 a_src + (size_t)(row0 + r) * NDIM + kk + lk4);
            cp16(bb + (unsigned int)(r * GSTRIDE + lk4) * 4u,
                 b_src + (size_t)(col0 + r) * NDIM + kk + lk4);
        }
        cp_commit();
    };

    load_tile(0, 0);

    for (int i = 0; i < GNIT; i++) {
        if (i + 1 < GNIT) {
            load_tile(i + 1, (i + 1) & 1);
            cp_wait<1>();
        } else {
            cp_wait<0>();
        }
        __syncthreads();

        unsigned int aB = asb + (unsigned int)((i & 1) * 128 * GSTRIDE) * 4u;
        unsigned int bB = bsb + (unsigned int)((i & 1) * 128 * GSTRIDE) * 4u;
#pragma unroll
        for (int ks = 0; ks < 2; ks++) {
            int kb = ks * 8;
            unsigned int af[4][4], bf[8][2];
#pragma unroll
            for (int mt = 0; mt < 4; mt++) {
                unsigned int ad = aB + (unsigned int)(((wm * 64 + mt * 16 + rselA) * GSTRIDE
                                                      + kb + kselA) * 4);
                ldsm4(af[mt][0], af[mt][1], af[mt][2], af[mt][3], ad);
#pragma unroll
                for (int q = 0; q < 4; q++) af[mt][q] = f2tf32(__uint_as_float(af[mt][q]));
            }
#pragma unroll
            for (int np = 0; np < 4; np++) {
                unsigned int bd = bB + (unsigned int)(((wn * 64 + np * 16 + cselB) * GSTRIDE
                                                      + kb + kselB) * 4);
                ldsm4(bf[2 * np][0], bf[2 * np][1], bf[2 * np + 1][0], bf[2 * np + 1][1], bd);
                bf[2 * np][0]     = f2tf32(__uint_as_float(bf[2 * np][0]));
                bf[2 * np][1]     = f2tf32(__uint_as_float(bf[2 * np][1]));
                bf[2 * np + 1][0] = f2tf32(__uint_as_float(bf[2 * np + 1][0]));
                bf[2 * np + 1][1] = f2tf32(__uint_as_float(bf[2 * np + 1][1]));
            }
#pragma unroll
            for (int mt = 0; mt < 4; mt++)
#pragma unroll
                for (int nt = 0; nt < 8; nt++)
                    mma_tf32(acc[mt][nt], af[mt], bf[nt]);
        }
        __syncthreads();
    }

#pragma unroll
    for (int nt = 0; nt < 8; nt++) {
        int c = col0 + wn * 64 + nt * 8 + tig * 2;
        float bv0 = __ldg(&B1[c]) + __ldg(&B2[c]);
        float bv1 = __ldg(&B1[c + 1]) + __ldg(&B2[c + 1]);
#pragma unroll
        for (int mt = 0; mt < 4; mt++) {
            int r = row0 + wm * 64 + mt * 16 + grp;
            float2 lo, hi;
            lo.x = sigmoidf_(acc[mt][nt][0] + bv0);
            lo.y = sigmoidf_(acc[mt][nt][1] + bv1);
            hi.x = sigmoidf_(acc[mt][nt][2] + bv0);
            hi.y = sigmoidf_(acc[mt][nt][3] + bv1);
            *(float2*)&G[(size_t)r * NDIM + c]       = lo;
            *(float2*)&G[(size_t)(r + 8) * NDIM + c] = hi;
        }
    }
}

// ---------------- fused elementwise layer update ----------------------------
__global__ void update_kernel(const float* __restrict__ w_r,
                              const float* __restrict__ w_i,
                              const float* __restrict__ raw_eta_l) {
    int idx = blockIdx.x * blockDim.x + threadIdx.x;
    if (idx >= TOTAL) return;
    int n = idx & (NDIM - 1);
    float reta = __ldg(raw_eta_l);
    float eta = (reta > 20.f) ? reta : log1pf(expf(reta));
    float dr = __ldg(&w_r[n]) + eta;
    float di = __ldg(&w_i[n]);
    float inv = 1.f / (dr * dr + di * di);

    float ahr = g_ahy_r[idx], ahi = g_ahy_i[idx];
    float zr = g_z_r[idx], zi = g_z_i[idx];
    float vr = g_v_r[idx], vi = g_v_i[idx];

    float nr = ahr + eta * (zr - vr);
    float ni = ahi + eta * (zi - vi);
    float xr = (nr * dr + ni * di) * inv;
    float xi = (ni * dr - nr * di) * inv;
    float ur = xr + vr, ui = xi + vi;

    float gr = g_g_r[idx], gi = g_g_i[idx];
    float znr = gr * ur - gi * ui + (1.f - gr) * zr + gi * zi;
    float zni = gr * ui + gi * ur + (1.f - gr) * zi - gi * zr;
    g_z_r[idx] = znr; g_z_i[idx] = zni;
    g_v_r[idx] = vr + xr - znr;
    g_v_i[idx] = vi + xi - zni;
}

// ---------------- final mask (real plane; defensive imag plane) -------------
__global__ void final_kernel(const float* thr, const float* alpha, int use_ptrs,
                             float* __restrict__ out, long long max_floats) {
    int idx = blockIdx.x * blockDim.x + threadIdx.x;
    if (idx >= TOTAL) return;
    float zr = g_z_r[idx], zi = g_z_i[idx];
    float amp = sqrtf(zr * zr + zi * zi);
    float t = use_ptrs ? *thr : 0.1f;
    float a = use_ptrs ? *alpha : 2.0f;
    float m = 1.f / (1.f + expf(-a * (amp - t)));
    if (idx < max_floats) out[idx] = zr * m;
    long long o = (long long)idx + TOTAL;
    if (o < max_floats) out[o] = zi * m;
}

// ---------------- launch ----------------------------------------------------
extern "C" void kernel_launch(void* const* d_in, const int* in_sizes, int n_in,
                              void* d_out, int out_size) {
    static const long long sig[17] = {SZ_BM, SZ_BM, SZ_BMN, SZ_BMN, SZ_LN, SZ_LN, SZ_L,
                                      SZ_LNN, SZ_LN, SZ_LNN, SZ_LN, SZ_LNN, SZ_LN,
                                      SZ_LNN, SZ_LN, 1, 1};
    static const long long srt[17] = {SZ_BMN, SZ_BMN, SZ_LN, SZ_LNN, SZ_LN, SZ_LNN,
                                      SZ_LN, SZ_LNN, SZ_LN, SZ_LNN, 1, SZ_L, 1,
                                      SZ_LN, SZ_LN, SZ_BM, SZ_BM};

    int map[17];
    int have_scalars = 0;
    int matched = 0;

    if (n_in == 17 || n_in == 15) {
        int ok = 1;
        for (int i = 0; i < n_in; i++)
            if ((long long)in_sizes[i] != sig[i]) { ok = 0; break; }
        if (ok) {
            for (int i = 0; i < 17; i++) map[i] = i;
            have_scalars = (n_in == 17);
            matched = 1;
        }
    }
    if (!matched && n_in == 17) {
        int ok = 1;
        for (int i = 0; i < 17; i++)
            if ((long long)in_sizes[i] != srt[i]) { ok = 0; break; }
        if (ok) {
            map[3] = 0;  map[2] = 1;  map[14] = 2; map[13] = 3; map[10] = 4;
            map[9] = 5;  map[12] = 6; map[11] = 7; map[8] = 8;  map[7] = 9;
            map[16] = 10; map[6] = 11; map[15] = 12; map[5] = 13; map[4] = 14;
            map[1] = 15; map[0] = 16;
            have_scalars = 1;
            matched = 2;
        }
    }
    if (!matched && n_in == 17) {
        int ok = 1;
        for (int i = 0; i < 17; i++)
            if ((long long)in_sizes[i] != sig[16 - i]) { ok = 0; break; }
        if (ok) {
            for (int i = 0; i < 17; i++) map[i] = 16 - i;
            have_scalars = 1;
            matched = 3;
        }
    }

    if (!matched) return;

    const float* y_r   = (const float*)d_in[map[0]];
    const float* y_i   = (const float*)d_in[map[1]];
    const float* A_r   = (const float*)d_in[map[2]];
    const float* A_i   = (const float*)d_in[map[3]];
    const float* wdr   = (const float*)d_in[map[4]];
    const float* wdi   = (const float*)d_in[map[5]];
    const float* reta  = (const float*)d_in[map[6]];
    const float* Wr    = (const float*)d_in[map[7]];
    const float* br    = (const float*)d_in[map[8]];
    const float* Ur    = (const float*)d_in[map[9]];
    const float* ubr   = (const float*)d_in[map[10]];
    const float* Wi    = (const float*)d_in[map[11]];
    const float* bi    = (const float*)d_in[map[12]];
    const float* Ui    = (const float*)d_in[map[13]];
    const float* ubi   = (const float*)d_in[map[14]];
    const float* thr   = have_scalars ? (const float*)d_in[map[15]] : (const float*)0;
    const float* alpha = have_scalars ? (const float*)d_in[map[16]] : (const float*)0;

    const int EW_BLOCKS = TOTAL / 256;

    zero_stats_kernel<<<1, 256>>>();
    ahy_kernel<<<BATCH, 256>>>(y_r, y_i, A_r, A_i);
    bn_reduce_kernel<<<BATCH / 128, 256>>>();
    bn_apply_layer0_kernel<<<EW_BLOCKS, 256>>>(wdr, wdi, reta, br, ubr, bi, ubi);

    for (int l = 1; l < L_LAYERS; l++) {
        size_t wo = (size_t)l * NDIM * NDIM;
        size_t bo = (size_t)l * NDIM;
        dim3 grid(NDIM / 128, BATCH / 128, 2);
        gate_gemm_tf32<<<grid, 128>>>(Wr + wo, Ur + wo, br + bo, ubr + bo,
                                      Wi + wo, Ui + wo, bi + bo, ubi + bo);
        update_kernel<<<EW_BLOCKS, 256>>>(wdr + bo, wdi + bo, reta + l);
    }

    final_kernel<<<EW_BLOCKS, 256>>>(thr, alpha, have_scalars,
                                     (float*)d_out, (long long)out_size);
}

// round 14
// speedup vs baseline: 1.6993x; 1.1437x over previous
#include <cuda_runtime.h>
#include <stdint.h>
#include <math.h>

#define L_LAYERS 10
#define NDIM 256
#define MDIM 64
#define BATCH 16384
#define BN_EPS 1e-5f

#define SZ_BM  (BATCH * MDIM)
#define SZ_BMN (1LL * BATCH * MDIM * NDIM)
#define SZ_LN  (L_LAYERS * NDIM)
#define SZ_LNN (1LL * L_LAYERS * NDIM * NDIM)
#define SZ_L   (L_LAYERS)
#define TOTAL  (BATCH * NDIM)

// ---------------- scratch ----------------------------------------------------
__device__ __align__(16) float g_ahy_r[TOTAL];
__device__ __align__(16) float g_ahy_i[TOTAL];
__device__ __align__(16) float g_z_r[TOTAL];
__device__ __align__(16) float g_z_i[TOTAL];
__device__ __align__(16) float g_v_r[TOTAL];
__device__ __align__(16) float g_v_i[TOTAL];
__device__ __align__(16) float g_g_r[TOTAL];
__device__ __align__(16) float g_g_i[TOTAL];
__device__ float g_sum_r[NDIM];
__device__ float g_ssq_r[NDIM];
__device__ float g_sum_i[NDIM];
__device__ float g_ssq_i[NDIM];

__device__ __forceinline__ float sigmoidf_(float x) { return 1.f / (1.f + expf(-x)); }

// ---------------- A^H y ------------------------------------------------------
__global__ void ahy_kernel(const float* __restrict__ y_r,
                           const float* __restrict__ y_i,
                           const float* __restrict__ A_r,
                           const float* __restrict__ A_i) {
    int b = blockIdx.x;
    int n = threadIdx.x;
    __shared__ float sy_r[MDIM];
    __shared__ float sy_i[MDIM];
    if (n < MDIM) sy_r[n] = y_r[b * MDIM + n];
    else if (n < 2 * MDIM) sy_i[n - MDIM] = y_i[b * MDIM + (n - MDIM)];
    __syncthreads();

    const float* Ar = A_r + (size_t)b * MDIM * NDIM + n;
    const float* Ai = A_i + (size_t)b * MDIM * NDIM + n;
    float sr = 0.f, si = 0.f;
#pragma unroll 8
    for (int m = 0; m < MDIM; m++) {
        float ar = Ar[(size_t)m * NDIM];
        float ai = Ai[(size_t)m * NDIM];
        float yr = sy_r[m], yi = sy_i[m];
        sr += ar * yr + ai * yi;
        si += ar * yi - ai * yr;
    }
    g_ahy_r[(size_t)b * NDIM + n] = sr;
    g_ahy_i[(size_t)b * NDIM + n] = si;
}

// ---------------- BatchNorm stats -------------------------------------------
__global__ void zero_stats_kernel() {
    int n = threadIdx.x;
    if (n < NDIM) {
        g_sum_r[n] = 0.f; g_ssq_r[n] = 0.f;
        g_sum_i[n] = 0.f; g_ssq_i[n] = 0.f;
    }
}

__global__ void bn_reduce_kernel() {
    int n = threadIdx.x;
    int r0 = blockIdx.x * 128;
    float sr = 0.f, qr = 0.f, si = 0.f, qi = 0.f;
#pragma unroll 4
    for (int r = 0; r < 128; r++) {
        float vr = g_ahy_r[(size_t)(r0 + r) * NDIM + n];
        float vi = g_ahy_i[(size_t)(r0 + r) * NDIM + n];
        sr += vr; qr += vr * vr;
        si += vi; qi += vi * vi;
    }
    atomicAdd(&g_sum_r[n], sr);
    atomicAdd(&g_ssq_r[n], qr);
    atomicAdd(&g_sum_i[n], si);
    atomicAdd(&g_ssq_i[n], qi);
}

// BN apply + fused analytic layer 0 (z=v=0)
__global__ void bn_apply_layer0_kernel(const float* __restrict__ wdr0,
                                       const float* __restrict__ wdi0,
                                       const float* __restrict__ reta,
                                       const float* __restrict__ br0,
                                       const float* __restrict__ ubr0,
                                       const float* __restrict__ bi0,
                                       const float* __restrict__ ubi0) {
    int idx = blockIdx.x * blockDim.x + threadIdx.x;
    if (idx >= TOTAL) return;
    int n = idx & (NDIM - 1);
    const float invB = 1.f / (float)BATCH;
    float mr = g_sum_r[n] * invB;
    float vr = g_ssq_r[n] * invB - mr * mr;
    float irr = rsqrtf(vr + BN_EPS);
    float mi = g_sum_i[n] * invB;
    float vi2 = g_ssq_i[n] * invB - mi * mi;
    float iri = rsqrtf(vi2 + BN_EPS);
    float ahr = (g_ahy_r[idx] - mr) * irr;
    float ahi = (g_ahy_i[idx] - mi) * iri;
    g_ahy_r[idx] = ahr;
    g_ahy_i[idx] = ahi;

    float re = __ldg(reta);
    float eta = (re > 20.f) ? re : log1pf(expf(re));
    float dr = __ldg(&wdr0[n]) + eta;
    float di = __ldg(&wdi0[n]);
    float inv = 1.f / (dr * dr + di * di);
    float xr = (ahr * dr + ahi * di) * inv;
    float xi = (ahi * dr - ahr * di) * inv;
    float gr = sigmoidf_(__ldg(&br0[n]) + __ldg(&ubr0[n]));
    float gi = sigmoidf_(__ldg(&bi0[n]) + __ldg(&ubi0[n]));
    float znr = gr * xr - gi * xi;
    float zni = gr * xi + gi * xr;
    g_z_r[idx] = znr; g_z_i[idx] = zni;
    g_v_r[idx] = xr - znr;
    g_v_i[idx] = xi - zni;
}

// ---------------- tf32 tensor-core gate GEMM --------------------------------
// G = sigmoid([Z|V] @ [W|U]^T + bW + bU), effective K = 512.
// CTA tile 128x128, BK=16, 8 warps of 64x32, 3-stage cp.async, 1 sync/iter.
// fp32 fed directly to mma.tf32 (HW truncates mantissa; no cvt instructions).
#define GK 16
#define GSTRIDE 20
#define GNIT 32
#define GSTAGES 3
#define GTILE (128 * GSTRIDE)                 // floats per (A or B) stage
#define GSMEM_FLOATS (2 * GSTAGES * GTILE)    // 61,440 floats = 245,760/4 bytes

__device__ __forceinline__ void cp16(unsigned int dst, const float* src) {
    asm volatile("cp.async.cg.shared.global [%0], [%1], 16;" :: "r"(dst), "l"(src));
}
__device__ __forceinline__ void cp_commit() {
    asm volatile("cp.async.commit_group;" ::: "memory");
}
template <int N>
__device__ __forceinline__ void cp_wait() {
    asm volatile("cp.async.wait_group %0;" :: "n"(N) : "memory");
}
__device__ __forceinline__ void ldsm4(unsigned int& r0, unsigned int& r1,
                                      unsigned int& r2, unsigned int& r3,
                                      unsigned int addr) {
    asm volatile("ldmatrix.sync.aligned.m8n8.x4.shared.b16 {%0,%1,%2,%3}, [%4];"
                 : "=r"(r0), "=r"(r1), "=r"(r2), "=r"(r3) : "r"(addr));
}
__device__ __forceinline__ void mma_tf32(float* c, const unsigned int* a,
                                         const unsigned int* b) {
    asm volatile(
        "mma.sync.aligned.m16n8k8.row.col.f32.tf32.tf32.f32 "
        "{%0,%1,%2,%3},{%4,%5,%6,%7},{%8,%9},{%0,%1,%2,%3};"
        : "+f"(c[0]), "+f"(c[1]), "+f"(c[2]), "+f"(c[3])
        : "r"(a[0]), "r"(a[1]), "r"(a[2]), "r"(a[3]), "r"(b[0]), "r"(b[1]));
}

__global__ __launch_bounds__(256, 2)
void gate_gemm_tf32(const float* __restrict__ Wr, const float* __restrict__ Ur,
                    const float* __restrict__ br, const float* __restrict__ ubr,
                    const float* __restrict__ Wi, const float* __restrict__ Ui,
                    const float* __restrict__ bi, const float* __restrict__ ubi) {
    const float* Z  = blockIdx.z ? g_z_i : g_z_r;
    const float* V  = blockIdx.z ? g_v_i : g_v_r;
    const float* W  = blockIdx.z ? Wi : Wr;
    const float* U  = blockIdx.z ? Ui : Ur;
    const float* B1 = blockIdx.z ? bi : br;
    const float* B2 = blockIdx.z ? ubi : ubr;
    float* G        = blockIdx.z ? g_g_i : g_g_r;

    extern __shared__ float sm[];
    float* As = sm;                       // [GSTAGES][GTILE]
    float* Bs = sm + GSTAGES * GTILE;     // [GSTAGES][GTILE]

    const int tid  = threadIdx.x;
    const int row0 = blockIdx.y * 128;
    const int col0 = blockIdx.x * 128;
    const int wid  = tid >> 5, lane = tid & 31;
    const int wm = wid >> 2;          // 0..1 : 64-row block
    const int wn = wid & 3;           // 0..3 : 32-col block
    const int grp = lane >> 2, tig = lane & 3;

    // ldmatrix lane address selectors (validated)
    const int rselA = (lane & 7) + ((lane >> 3) & 1) * 8;
    const int kselA = (lane >> 4) * 4;
    const int cselB = (lane & 7) + (lane >> 4) * 8;
    const int kselB = ((lane >> 3) & 1) * 4;

    const int lrow = tid >> 2;        // 0..63
    const int lk4  = (tid & 3) * 4;   // 0,4,8,12

    float acc[4][4][4];
#pragma unroll
    for (int a = 0; a < 4; a++)
#pragma unroll
        for (int b = 0; b < 4; b++)
#pragma unroll
            for (int c = 0; c < 4; c++) acc[a][b][c] = 0.f;

    unsigned int asb = (unsigned int)__cvta_generic_to_shared(As);
    unsigned int bsb = (unsigned int)__cvta_generic_to_shared(Bs);

    auto load_tile = [&](int it, int buf) {
        int kg = it * GK;
        const float* a_src = (kg < 256) ? Z : V;
        const float* b_src = (kg < 256) ? W : U;
        int kk = kg & 255;
        unsigned int ab = asb + (unsigned int)(buf * GTILE) * 4u;
        unsigned int bb = bsb + (unsigned int)(buf * GTILE) * 4u;
#pragma unroll
        for (int j = 0; j < 2; j++) {
            int r = lrow + j * 64;
            unsigned int so = (unsigned int)((r * GSTRIDE + lk4) * 4);
            cp16(ab + so, a_src + (size_t)(row0 + r) * NDIM + kk + lk4);
            cp16(bb + so, b_src + (size_t)(col0 + r) * NDIM + kk + lk4);
        }
        cp_commit();
    };

    load_tile(0, 0);
    load_tile(1, 1);

    int buf = 0;
    for (int i = 0; i < GNIT; i++) {
        cp_wait<1>();
        __syncthreads();

        unsigned int aB = asb + (unsigned int)(buf * GTILE) * 4u;
        unsigned int bB = bsb + (unsigned int)(buf * GTILE) * 4u;
#pragma unroll
        for (int ks = 0; ks < 2; ks++) {
            int kb = ks * 8;
            unsigned int af[4][4], bf[4][2];
#pragma unroll
            for (int mt = 0; mt < 4; mt++) {
                unsigned int ad = aB + (unsigned int)(((wm * 64 + mt * 16 + rselA) * GSTRIDE
                                                      + kb + kselA) * 4);
                ldsm4(af[mt][0], af[mt][1], af[mt][2], af[mt][3], ad);
            }
#pragma unroll
            for (int np = 0; np < 2; np++) {
                unsigned int bd = bB + (unsigned int)(((wn * 32 + np * 16 + cselB) * GSTRIDE
                                                      + kb + kselB) * 4);
                ldsm4(bf[2 * np][0], bf[2 * np][1], bf[2 * np + 1][0], bf[2 * np + 1][1], bd);
            }
#pragma unroll
            for (int mt = 0; mt < 4; mt++)
#pragma unroll
                for (int nt = 0; nt < 4; nt++)
                    mma_tf32(acc[mt][nt], af[mt], bf[nt]);
        }

        if (i + 2 < GNIT) load_tile(i + 2, (i + 2) % GSTAGES);
        buf = (buf + 1) % GSTAGES;
    }

    // epilogue: bias + sigmoid, float2 stores
#pragma unroll
    for (int nt = 0; nt < 4; nt++) {
        int c = col0 + wn * 32 + nt * 8 + tig * 2;
        float bv0 = __ldg(&B1[c]) + __ldg(&B2[c]);
        float bv1 = __ldg(&B1[c + 1]) + __ldg(&B2[c + 1]);
#pragma unroll
        for (int mt = 0; mt < 4; mt++) {
            int r = row0 + wm * 64 + mt * 16 + grp;
            float2 lo, hi;
            lo.x = sigmoidf_(acc[mt][nt][0] + bv0);
            lo.y = sigmoidf_(acc[mt][nt][1] + bv1);
            hi.x = sigmoidf_(acc[mt][nt][2] + bv0);
            hi.y = sigmoidf_(acc[mt][nt][3] + bv1);
            *(float2*)&G[(size_t)r * NDIM + c]       = lo;
            *(float2*)&G[(size_t)(r + 8) * NDIM + c] = hi;
        }
    }
}

// ---------------- fused elementwise layer update ----------------------------
__global__ void update_kernel(const float* __restrict__ w_r,
                              const float* __restrict__ w_i,
                              const float* __restrict__ raw_eta_l) {
    int idx = blockIdx.x * blockDim.x + threadIdx.x;
    if (idx >= TOTAL) return;
    int n = idx & (NDIM - 1);
    float reta = __ldg(raw_eta_l);
    float eta = (reta > 20.f) ? reta : log1pf(expf(reta));
    float dr = __ldg(&w_r[n]) + eta;
    float di = __ldg(&w_i[n]);
    float inv = 1.f / (dr * dr + di * di);

    float ahr = g_ahy_r[idx], ahi = g_ahy_i[idx];
    float zr = g_z_r[idx], zi = g_z_i[idx];
    float vr = g_v_r[idx], vi = g_v_i[idx];

    float nr = ahr + eta * (zr - vr);
    float ni = ahi + eta * (zi - vi);
    float xr = (nr * dr + ni * di) * inv;
    float xi = (ni * dr - nr * di) * inv;
    float ur = xr + vr, ui = xi + vi;

    float gr = g_g_r[idx], gi = g_g_i[idx];
    float znr = gr * ur - gi * ui + (1.f - gr) * zr + gi * zi;
    float zni = gr * ui + gi * ur + (1.f - gr) * zi - gi * zr;
    g_z_r[idx] = znr; g_z_i[idx] = zni;
    g_v_r[idx] = vr + xr - znr;
    g_v_i[idx] = vi + xi - zni;
}

// ---------------- final mask (real plane; defensive imag plane) -------------
__global__ void final_kernel(const float* thr, const float* alpha, int use_ptrs,
                             float* __restrict__ out, long long max_floats) {
    int idx = blockIdx.x * blockDim.x + threadIdx.x;
    if (idx >= TOTAL) return;
    float zr = g_z_r[idx], zi = g_z_i[idx];
    float amp = sqrtf(zr * zr + zi * zi);
    float t = use_ptrs ? *thr : 0.1f;
    float a = use_ptrs ? *alpha : 2.0f;
    float m = 1.f / (1.f + expf(-a * (amp - t)));
    if (idx < max_floats) out[idx] = zr * m;
    long long o = (long long)idx + TOTAL;
    if (o < max_floats) out[o] = zi * m;
}

// ---------------- launch ----------------------------------------------------
extern "C" void kernel_launch(void* const* d_in, const int* in_sizes, int n_in,
                              void* d_out, int out_size) {
    static const long long sig[17] = {SZ_BM, SZ_BM, SZ_BMN, SZ_BMN, SZ_LN, SZ_LN, SZ_L,
                                      SZ_LNN, SZ_LN, SZ_LNN, SZ_LN, SZ_LNN, SZ_LN,
                                      SZ_LNN, SZ_LN, 1, 1};
    static const long long srt[17] = {SZ_BMN, SZ_BMN, SZ_LN, SZ_LNN, SZ_LN, SZ_LNN,
                                      SZ_LN, SZ_LNN, SZ_LN, SZ_LNN, 1, SZ_L, 1,
                                      SZ_LN, SZ_LN, SZ_BM, SZ_BM};

    int map[17];
    int have_scalars = 0;
    int matched = 0;

    if (n_in == 17 || n_in == 15) {
        int ok = 1;
        for (int i = 0; i < n_in; i++)
            if ((long long)in_sizes[i] != sig[i]) { ok = 0; break; }
        if (ok) {
            for (int i = 0; i < 17; i++) map[i] = i;
            have_scalars = (n_in == 17);
            matched = 1;
        }
    }
    if (!matched && n_in == 17) {
        int ok = 1;
        for (int i = 0; i < 17; i++)
            if ((long long)in_sizes[i] != srt[i]) { ok = 0; break; }
        if (ok) {
            map[3] = 0;  map[2] = 1;  map[14] = 2; map[13] = 3; map[10] = 4;
            map[9] = 5;  map[12] = 6; map[11] = 7; map[8] = 8;  map[7] = 9;
            map[16] = 10; map[6] = 11; map[15] = 12; map[5] = 13; map[4] = 14;
            map[1] = 15; map[0] = 16;
            have_scalars = 1;
            matched = 2;
        }
    }
    if (!matched && n_in == 17) {
        int ok = 1;
        for (int i = 0; i < 17; i++)
            if ((long long)in_sizes[i] != sig[16 - i]) { ok = 0; break; }
        if (ok) {
            for (int i = 0; i < 17; i++) map[i] = 16 - i;
            have_scalars = 1;
            matched = 3;
        }
    }

    if (!matched) return;

    const float* y_r   = (const float*)d_in[map[0]];
    const float* y_i   = (const float*)d_in[map[1]];
    const float* A_r   = (const float*)d_in[map[2]];
    const float* A_i   = (const float*)d_in[map[3]];
    const float* wdr   = (const float*)d_in[map[4]];
    const float* wdi   = (const float*)d_in[map[5]];
    const float* reta  = (const float*)d_in[map[6]];
    const float* Wr    = (const float*)d_in[map[7]];
    const float* br    = (const float*)d_in[map[8]];
    const float* Ur    = (const float*)d_in[map[9]];
    const float* ubr   = (const float*)d_in[map[10]];
    const float* Wi    = (const float*)d_in[map[11]];
    const float* bi    = (const float*)d_in[map[12]];
    const float* Ui    = (const float*)d_in[map[13]];
    const float* ubi   = (const float*)d_in[map[14]];
    const float* thr   = have_scalars ? (const float*)d_in[map[15]] : (const float*)0;
    const float* alpha = have_scalars ? (const float*)d_in[map[16]] : (const float*)0;

    const int EW_BLOCKS = TOTAL / 256;
    const int SMEM_BYTES = GSMEM_FLOATS * 4;

    cudaFuncSetAttribute(gate_gemm_tf32,
                         cudaFuncAttributeMaxDynamicSharedMemorySize, SMEM_BYTES);

    zero_stats_kernel<<<1, 256>>>();
    ahy_kernel<<<BATCH, 256>>>(y_r, y_i, A_r, A_i);
    bn_reduce_kernel<<<BATCH / 128, 256>>>();
    bn_apply_layer0_kernel<<<EW_BLOCKS, 256>>>(wdr, wdi, reta, br, ubr, bi, ubi);

    for (int l = 1; l < L_LAYERS; l++) {
        size_t wo = (size_t)l * NDIM * NDIM;
        size_t bo = (size_t)l * NDIM;
        dim3 grid(NDIM / 128, BATCH / 128, 2);
        gate_gemm_tf32<<<grid, 256, SMEM_BYTES>>>(Wr + wo, Ur + wo, br + bo, ubr + bo,
                                                  Wi + wo, Ui + wo, bi + bo, ubi + bo);
        update_kernel<<<EW_BLOCKS, 256>>>(wdr + bo, wdi + bo, reta + l);
    }

    final_kernel<<<EW_BLOCKS, 256>>>(thr, alpha, have_scalars,
                                     (float*)d_out, (long long)out_size);
}

// round 16
// speedup vs baseline: 1.9492x; 1.1470x over previous
#include <cuda_runtime.h>
#include <cuda_bf16.h>
#include <stdint.h>
#include <math.h>

#define L_LAYERS 10
#define NDIM 256
#define MDIM 64
#define BATCH 16384
#define BN_EPS 1e-5f

#define SZ_BM  (BATCH * MDIM)
#define SZ_BMN (1LL * BATCH * MDIM * NDIM)
#define SZ_LN  (L_LAYERS * NDIM)
#define SZ_LNN (1LL * L_LAYERS * NDIM * NDIM)
#define SZ_L   (L_LAYERS)
#define TOTAL  (BATCH * NDIM)
#define LNN    (L_LAYERS * NDIM * NDIM)

// ---------------- scratch ----------------------------------------------------
__device__ __align__(16) float g_ahy_r[TOTAL];
__device__ __align__(16) float g_ahy_i[TOTAL];
__device__ __align__(16) float g_z_r[TOTAL];
__device__ __align__(16) float g_z_i[TOTAL];
__device__ __align__(16) float g_v_r[TOTAL];
__device__ __align__(16) float g_v_i[TOTAL];
__device__ __align__(16) float g_g_r[TOTAL];
__device__ __align__(16) float g_g_i[TOTAL];
// bf16 mirrors of MMA inputs (fp32 remains the master state)
__device__ __align__(16) __nv_bfloat16 g_zb_r[TOTAL];
__device__ __align__(16) __nv_bfloat16 g_zb_i[TOTAL];
__device__ __align__(16) __nv_bfloat16 g_vb_r[TOTAL];
__device__ __align__(16) __nv_bfloat16 g_vb_i[TOTAL];
__device__ __align__(16) __nv_bfloat16 g_wb_r[LNN];  // Wg_r
__device__ __align__(16) __nv_bfloat16 g_ub_r[LNN];  // Ug_r
__device__ __align__(16) __nv_bfloat16 g_wb_i[LNN];  // Wg_i
__device__ __align__(16) __nv_bfloat16 g_ub_i[LNN];  // Ug_i
__device__ float g_sum_r[NDIM];
__device__ float g_ssq_r[NDIM];
__device__ float g_sum_i[NDIM];
__device__ float g_ssq_i[NDIM];

__device__ __forceinline__ float sigmoidf_(float x) { return 1.f / (1.f + expf(-x)); }

// ---------------- weights -> bf16 (once per run) -----------------------------
__global__ void convert_weights_kernel(const float* __restrict__ Wr,
                                       const float* __restrict__ Ur,
                                       const float* __restrict__ Wi,
                                       const float* __restrict__ Ui) {
    int i = blockIdx.x * blockDim.x + threadIdx.x;
    if (i >= LNN) return;
    g_wb_r[i] = __float2bfloat16(Wr[i]);
    g_ub_r[i] = __float2bfloat16(Ur[i]);
    g_wb_i[i] = __float2bfloat16(Wi[i]);
    g_ub_i[i] = __float2bfloat16(Ui[i]);
}

// ---------------- A^H y ------------------------------------------------------
__global__ void ahy_kernel(const float* __restrict__ y_r,
                           const float* __restrict__ y_i,
                           const float* __restrict__ A_r,
                           const float* __restrict__ A_i) {
    int b = blockIdx.x;
    int n = threadIdx.x;
    __shared__ float sy_r[MDIM];
    __shared__ float sy_i[MDIM];
    if (n < MDIM) sy_r[n] = y_r[b * MDIM + n];
    else if (n < 2 * MDIM) sy_i[n - MDIM] = y_i[b * MDIM + (n - MDIM)];
    __syncthreads();

    const float* Ar = A_r + (size_t)b * MDIM * NDIM + n;
    const float* Ai = A_i + (size_t)b * MDIM * NDIM + n;
    float sr = 0.f, si = 0.f;
#pragma unroll 8
    for (int m = 0; m < MDIM; m++) {
        float ar = Ar[(size_t)m * NDIM];
        float ai = Ai[(size_t)m * NDIM];
        float yr = sy_r[m], yi = sy_i[m];
        sr += ar * yr + ai * yi;
        si += ar * yi - ai * yr;
    }
    g_ahy_r[(size_t)b * NDIM + n] = sr;
    g_ahy_i[(size_t)b * NDIM + n] = si;
}

// ---------------- BatchNorm stats -------------------------------------------
__global__ void zero_stats_kernel() {
    int n = threadIdx.x;
    if (n < NDIM) {
        g_sum_r[n] = 0.f; g_ssq_r[n] = 0.f;
        g_sum_i[n] = 0.f; g_ssq_i[n] = 0.f;
    }
}

__global__ void bn_reduce_kernel() {
    int n = threadIdx.x;
    int r0 = blockIdx.x * 128;
    float sr = 0.f, qr = 0.f, si = 0.f, qi = 0.f;
#pragma unroll 4
    for (int r = 0; r < 128; r++) {
        float vr = g_ahy_r[(size_t)(r0 + r) * NDIM + n];
        float vi = g_ahy_i[(size_t)(r0 + r) * NDIM + n];
        sr += vr; qr += vr * vr;
        si += vi; qi += vi * vi;
    }
    atomicAdd(&g_sum_r[n], sr);
    atomicAdd(&g_ssq_r[n], qr);
    atomicAdd(&g_sum_i[n], si);
    atomicAdd(&g_ssq_i[n], qi);
}

// BN apply + fused analytic layer 0 (z=v=0); also writes bf16 state mirrors
__global__ void bn_apply_layer0_kernel(const float* __restrict__ wdr0,
                                       const float* __restrict__ wdi0,
                                       const float* __restrict__ reta,
                                       const float* __restrict__ br0,
                                       const float* __restrict__ ubr0,
                                       const float* __restrict__ bi0,
                                       const float* __restrict__ ubi0) {
    int idx = blockIdx.x * blockDim.x + threadIdx.x;
    if (idx >= TOTAL) return;
    int n = idx & (NDIM - 1);
    const float invB = 1.f / (float)BATCH;
    float mr = g_sum_r[n] * invB;
    float vr = g_ssq_r[n] * invB - mr * mr;
    float irr = rsqrtf(vr + BN_EPS);
    float mi = g_sum_i[n] * invB;
    float vi2 = g_ssq_i[n] * invB - mi * mi;
    float iri = rsqrtf(vi2 + BN_EPS);
    float ahr = (g_ahy_r[idx] - mr) * irr;
    float ahi = (g_ahy_i[idx] - mi) * iri;
    g_ahy_r[idx] = ahr;
    g_ahy_i[idx] = ahi;

    float re = __ldg(reta);
    float eta = (re > 20.f) ? re : log1pf(expf(re));
    float dr = __ldg(&wdr0[n]) + eta;
    float di = __ldg(&wdi0[n]);
    float inv = 1.f / (dr * dr + di * di);
    float xr = (ahr * dr + ahi * di) * inv;
    float xi = (ahi * dr - ahr * di) * inv;
    float gr = sigmoidf_(__ldg(&br0[n]) + __ldg(&ubr0[n]));
    float gi = sigmoidf_(__ldg(&bi0[n]) + __ldg(&ubi0[n]));
    float znr = gr * xr - gi * xi;
    float zni = gr * xi + gi * xr;
    float vnr = xr - znr, vni = xi - zni;
    g_z_r[idx] = znr; g_z_i[idx] = zni;
    g_v_r[idx] = vnr; g_v_i[idx] = vni;
    g_zb_r[idx] = __float2bfloat16(znr);
    g_zb_i[idx] = __float2bfloat16(zni);
    g_vb_r[idx] = __float2bfloat16(vnr);
    g_vb_i[idx] = __float2bfloat16(vni);
}

// ---------------- bf16 tensor-core gate GEMM --------------------------------
// G = sigmoid([Z|V] @ [W|U]^T + bW + bU), effective K = 512.
// CTA tile 128x128, BK=32 bf16, 8 warps of 64x32, mma.m16n8k16, 3-stage cp.async.
#define GK 32
#define GSTRIDE 40                       // bf16 units per smem row (80B, conflict-free)
#define GNIT 16                          // 512 / 32
#define GSTAGES 3
#define GTILE_B (128 * GSTRIDE * 2)      // bytes per (A or B) stage = 10240
#define GSMEM_BYTES (2 * GSTAGES * GTILE_B)   // 61,440 B

__device__ __forceinline__ void cp16(unsigned int dst, const void* src) {
    asm volatile("cp.async.cg.shared.global [%0], [%1], 16;" :: "r"(dst), "l"(src));
}
__device__ __forceinline__ void cp_commit() {
    asm volatile("cp.async.commit_group;" ::: "memory");
}
template <int N>
__device__ __forceinline__ void cp_wait() {
    asm volatile("cp.async.wait_group %0;" :: "n"(N) : "memory");
}
__device__ __forceinline__ void ldsm4(unsigned int& r0, unsigned int& r1,
                                      unsigned int& r2, unsigned int& r3,
                                      unsigned int addr) {
    asm volatile("ldmatrix.sync.aligned.m8n8.x4.shared.b16 {%0,%1,%2,%3}, [%4];"
                 : "=r"(r0), "=r"(r1), "=r"(r2), "=r"(r3) : "r"(addr));
}
__device__ __forceinline__ void mma_bf16(float* c, const unsigned int* a,
                                         const unsigned int* b) {
    asm volatile(
        "mma.sync.aligned.m16n8k16.row.col.f32.bf16.bf16.f32 "
        "{%0,%1,%2,%3},{%4,%5,%6,%7},{%8,%9},{%0,%1,%2,%3};"
        : "+f"(c[0]), "+f"(c[1]), "+f"(c[2]), "+f"(c[3])
        : "r"(a[0]), "r"(a[1]), "r"(a[2]), "r"(a[3]), "r"(b[0]), "r"(b[1]));
}

__global__ __launch_bounds__(256, 2)
void gate_gemm_bf16(int layer,
                    const float* __restrict__ br, const float* __restrict__ ubr,
                    const float* __restrict__ bi, const float* __restrict__ ubi) {
    const size_t wo = (size_t)layer * NDIM * NDIM;
    const __nv_bfloat16* Z = blockIdx.z ? g_zb_i : g_zb_r;
    const __nv_bfloat16* V = blockIdx.z ? g_vb_i : g_vb_r;
    const __nv_bfloat16* W = (blockIdx.z ? g_wb_i : g_wb_r) + wo;
    const __nv_bfloat16* U = (blockIdx.z ? g_ub_i : g_ub_r) + wo;
    const float* B1 = blockIdx.z ? bi : br;
    const float* B2 = blockIdx.z ? ubi : ubr;
    float* G        = blockIdx.z ? g_g_i : g_g_r;

    extern __shared__ __nv_bfloat16 smb16[];
    __nv_bfloat16* As = smb16;                            // [GSTAGES][128*GSTRIDE]
    __nv_bfloat16* Bs = smb16 + GSTAGES * 128 * GSTRIDE;  // [GSTAGES][128*GSTRIDE]

    const int tid  = threadIdx.x;
    const int row0 = blockIdx.y * 128;
    const int col0 = blockIdx.x * 128;
    const int wid  = tid >> 5, lane = tid & 31;
    const int wm = wid >> 2;          // 0..1 : 64-row block
    const int wn = wid & 3;           // 0..3 : 32-col block
    const int grp = lane >> 2, tig = lane & 3;

    // ldmatrix lane selectors (b16-native): row/col index + 16-byte k-half offset
    const int rselA = (lane & 7) + ((lane >> 3) & 1) * 8;
    const int kbA   = (lane >> 4) * 16;          // byte offset within k (8 bf16)
    const int cselB = (lane & 7) + (lane >> 4) * 8;
    const int kbB   = ((lane >> 3) & 1) * 16;

    const int lrow = tid >> 1;        // 0..127
    const int lkc  = (tid & 1) * 16;  // bf16 units (2 x 16B chunks per thread)

    float acc[4][4][4];
#pragma unroll
    for (int a = 0; a < 4; a++)
#pragma unroll
        for (int b = 0; b < 4; b++)
#pragma unroll
            for (int c = 0; c < 4; c++) acc[a][b][c] = 0.f;

    unsigned int asb = (unsigned int)__cvta_generic_to_shared(As);
    unsigned int bsb = (unsigned int)__cvta_generic_to_shared(Bs);

    auto load_tile = [&](int it, int buf) {
        int kg = it * GK;
        const __nv_bfloat16* a_src = (kg < 256) ? Z : V;
        const __nv_bfloat16* b_src = (kg < 256) ? W : U;
        int kk = kg & 255;
        unsigned int ab = asb + (unsigned int)(buf * GTILE_B);
        unsigned int bb = bsb + (unsigned int)(buf * GTILE_B);
        unsigned int so = (unsigned int)((lrow * GSTRIDE + lkc) * 2);
        const __nv_bfloat16* ag = a_src + (size_t)(row0 + lrow) * NDIM + kk + lkc;
        const __nv_bfloat16* bg = b_src + (size_t)(col0 + lrow) * NDIM + kk + lkc;
        cp16(ab + so,      ag);
        cp16(ab + so + 16, ag + 8);
        cp16(bb + so,      bg);
        cp16(bb + so + 16, bg + 8);
        cp_commit();
    };

    load_tile(0, 0);
    load_tile(1, 1);

    int buf = 0;
    for (int i = 0; i < GNIT; i++) {
        cp_wait<1>();
        __syncthreads();

        unsigned int aB = asb + (unsigned int)(buf * GTILE_B);
        unsigned int bB = bsb + (unsigned int)(buf * GTILE_B);
#pragma unroll
        for (int ks = 0; ks < 2; ks++) {
            int kb = ks * 16;  // bf16 units
            unsigned int af[4][4], bf[4][2];
#pragma unroll
            for (int mt = 0; mt < 4; mt++) {
                unsigned int ad = aB + (unsigned int)(((wm * 64 + mt * 16 + rselA) * GSTRIDE
                                                      + kb) * 2 + kbA);
                ldsm4(af[mt][0], af[mt][1], af[mt][2], af[mt][3], ad);
            }
#pragma unroll
            for (int np = 0; np < 2; np++) {
                unsigned int bd = bB + (unsigned int)(((wn * 32 + np * 16 + cselB) * GSTRIDE
                                                      + kb) * 2 + kbB);
                ldsm4(bf[2 * np][0], bf[2 * np][1], bf[2 * np + 1][0], bf[2 * np + 1][1], bd);
            }
#pragma unroll
            for (int mt = 0; mt < 4; mt++)
#pragma unroll
                for (int nt = 0; nt < 4; nt++)
                    mma_bf16(acc[mt][nt], af[mt], bf[nt]);
        }

        if (i + 2 < GNIT) load_tile(i + 2, (i + 2) % GSTAGES);
        buf = (buf + 1) % GSTAGES;
    }

    // epilogue: bias + sigmoid, float2 stores
#pragma unroll
    for (int nt = 0; nt < 4; nt++) {
        int c = col0 + wn * 32 + nt * 8 + tig * 2;
        float bv0 = __ldg(&B1[c]) + __ldg(&B2[c]);
        float bv1 = __ldg(&B1[c + 1]) + __ldg(&B2[c + 1]);
#pragma unroll
        for (int mt = 0; mt < 4; mt++) {
            int r = row0 + wm * 64 + mt * 16 + grp;
            float2 lo, hi;
            lo.x = sigmoidf_(acc[mt][nt][0] + bv0);
            lo.y = sigmoidf_(acc[mt][nt][1] + bv1);
            hi.x = sigmoidf_(acc[mt][nt][2] + bv0);
            hi.y = sigmoidf_(acc[mt][nt][3] + bv1);
            *(float2*)&G[(size_t)r * NDIM + c]       = lo;
            *(float2*)&G[(size_t)(r + 8) * NDIM + c] = hi;
        }
    }
}

// ---------------- fused elementwise layer update ----------------------------
__global__ void update_kernel(const float* __restrict__ w_r,
                              const float* __restrict__ w_i,
                              const float* __restrict__ raw_eta_l) {
    int idx = blockIdx.x * blockDim.x + threadIdx.x;
    if (idx >= TOTAL) return;
    int n = idx & (NDIM - 1);
    float reta = __ldg(raw_eta_l);
    float eta = (reta > 20.f) ? reta : log1pf(expf(reta));
    float dr = __ldg(&w_r[n]) + eta;
    float di = __ldg(&w_i[n]);
    float inv = 1.f / (dr * dr + di * di);

    float ahr = g_ahy_r[idx], ahi = g_ahy_i[idx];
    float zr = g_z_r[idx], zi = g_z_i[idx];
    float vr = g_v_r[idx], vi = g_v_i[idx];

    float nr = ahr + eta * (zr - vr);
    float ni = ahi + eta * (zi - vi);
    float xr = (nr * dr + ni * di) * inv;
    float xi = (ni * dr - nr * di) * inv;
    float ur = xr + vr, ui = xi + vi;

    float gr = g_g_r[idx], gi = g_g_i[idx];
    float znr = gr * ur - gi * ui + (1.f - gr) * zr + gi * zi;
    float zni = gr * ui + gi * ur + (1.f - gr) * zi - gi * zr;
    float vnr = vr + xr - znr;
    float vni = vi + xi - zni;
    g_z_r[idx] = znr; g_z_i[idx] = zni;
    g_v_r[idx] = vnr; g_v_i[idx] = vni;
    g_zb_r[idx] = __float2bfloat16(znr);
    g_zb_i[idx] = __float2bfloat16(zni);
    g_vb_r[idx] = __float2bfloat16(vnr);
    g_vb_i[idx] = __float2bfloat16(vni);
}

// ---------------- final mask (real plane; defensive imag plane) -------------
__global__ void final_kernel(const float* thr, const float* alpha, int use_ptrs,
                             float* __restrict__ out, long long max_floats) {
    int idx = blockIdx.x * blockDim.x + threadIdx.x;
    if (idx >= TOTAL) return;
    float zr = g_z_r[idx], zi = g_z_i[idx];
    float amp = sqrtf(zr * zr + zi * zi);
    float t = use_ptrs ? *thr : 0.1f;
    float a = use_ptrs ? *alpha : 2.0f;
    float m = 1.f / (1.f + expf(-a * (amp - t)));
    if (idx < max_floats) out[idx] = zr * m;
    long long o = (long long)idx + TOTAL;
    if (o < max_floats) out[o] = zi * m;
}

// ---------------- launch ----------------------------------------------------
extern "C" void kernel_launch(void* const* d_in, const int* in_sizes, int n_in,
                              void* d_out, int out_size) {
    static const long long sig[17] = {SZ_BM, SZ_BM, SZ_BMN, SZ_BMN, SZ_LN, SZ_LN, SZ_L,
                                      SZ_LNN, SZ_LN, SZ_LNN, SZ_LN, SZ_LNN, SZ_LN,
                                      SZ_LNN, SZ_LN, 1, 1};
    static const long long srt[17] = {SZ_BMN, SZ_BMN, SZ_LN, SZ_LNN, SZ_LN, SZ_LNN,
                                      SZ_LN, SZ_LNN, SZ_LN, SZ_LNN, 1, SZ_L, 1,
                                      SZ_LN, SZ_LN, SZ_BM, SZ_BM};

    int map[17];
    int have_scalars = 0;
    int matched = 0;

    if (n_in == 17 || n_in == 15) {
        int ok = 1;
        for (int i = 0; i < n_in; i++)
            if ((long long)in_sizes[i] != sig[i]) { ok = 0; break; }
        if (ok) {
            for (int i = 0; i < 17; i++) map[i] = i;
            have_scalars = (n_in == 17);
            matched = 1;
        }
    }
    if (!matched && n_in == 17) {
        int ok = 1;
        for (int i = 0; i < 17; i++)
            if ((long long)in_sizes[i] != srt[i]) { ok = 0; break; }
        if (ok) {
            map[3] = 0;  map[2] = 1;  map[14] = 2; map[13] = 3; map[10] = 4;
            map[9] = 5;  map[12] = 6; map[11] = 7; map[8] = 8;  map[7] = 9;
            map[16] = 10; map[6] = 11; map[15] = 12; map[5] = 13; map[4] = 14;
            map[1] = 15; map[0] = 16;
            have_scalars = 1;
            matched = 2;
        }
    }
    if (!matched && n_in == 17) {
        int ok = 1;
        for (int i = 0; i < 17; i++)
            if ((long long)in_sizes[i] != sig[16 - i]) { ok = 0; break; }
        if (ok) {
            for (int i = 0; i < 17; i++) map[i] = 16 - i;
            have_scalars = 1;
            matched = 3;
        }
    }

    if (!matched) return;

    const float* y_r   = (const float*)d_in[map[0]];
    const float* y_i   = (const float*)d_in[map[1]];
    const float* A_r   = (const float*)d_in[map[2]];
    const float* A_i   = (const float*)d_in[map[3]];
    const float* wdr   = (const float*)d_in[map[4]];
    const float* wdi   = (const float*)d_in[map[5]];
    const float* reta  = (const float*)d_in[map[6]];
    const float* Wr    = (const float*)d_in[map[7]];
    const float* br    = (const float*)d_in[map[8]];
    const float* Ur    = (const float*)d_in[map[9]];
    const float* ubr   = (const float*)d_in[map[10]];
    const float* Wi    = (const float*)d_in[map[11]];
    const float* bi    = (const float*)d_in[map[12]];
    const float* Ui    = (const float*)d_in[map[13]];
    const float* ubi   = (const float*)d_in[map[14]];
    const float* thr   = have_scalars ? (const float*)d_in[map[15]] : (const float*)0;
    const float* alpha = have_scalars ? (const float*)d_in[map[16]] : (const float*)0;

    const int EW_BLOCKS = TOTAL / 256;

    cudaFuncSetAttribute(gate_gemm_bf16,
                         cudaFuncAttributeMaxDynamicSharedMemorySize, GSMEM_BYTES);

    convert_weights_kernel<<<(LNN + 255) / 256, 256>>>(Wr, Ur, Wi, Ui);
    zero_stats_kernel<<<1, 256>>>();
    ahy_kernel<<<BATCH, 256>>>(y_r, y_i, A_r, A_i);
    bn_reduce_kernel<<<BATCH / 128, 256>>>();
    bn_apply_layer0_kernel<<<EW_BLOCKS, 256>>>(wdr, wdi, reta, br, ubr, bi, ubi);

    for (int l = 1; l < L_LAYERS; l++) {
        size_t bo = (size_t)l * NDIM;
        dim3 grid(NDIM / 128, BATCH / 128, 2);
        gate_gemm_bf16<<<grid, 256, GSMEM_BYTES>>>(l, br + bo, ubr + bo,
                                                   bi + bo, ubi + bo);
        update_kernel<<<EW_BLOCKS, 256>>>(wdr + bo, wdi + bo, reta + l);
    }

    final_kernel<<<EW_BLOCKS, 256>>>(thr, alpha, have_scalars,
                                     (float*)d_out, (long long)out_size);
}

// round 17
// speedup vs baseline: 2.0434x; 1.0483x over previous
#include <cuda_runtime.h>
#include <cuda_bf16.h>
#include <stdint.h>
#include <math.h>

#define L_LAYERS 10
#define NDIM 256
#define MDIM 64
#define BATCH 16384
#define BN_EPS 1e-5f

#define SZ_BM  (BATCH * MDIM)
#define SZ_BMN (1LL * BATCH * MDIM * NDIM)
#define SZ_LN  (L_LAYERS * NDIM)
#define SZ_LNN (1LL * L_LAYERS * NDIM * NDIM)
#define SZ_L   (L_LAYERS)
#define TOTAL  (BATCH * NDIM)
#define LNN    (L_LAYERS * NDIM * NDIM)

// ---------------- scratch ----------------------------------------------------
__device__ __align__(16) float g_ahy_r[TOTAL];
__device__ __align__(16) float g_ahy_i[TOTAL];
__device__ __align__(16) float g_z_r[TOTAL];
__device__ __align__(16) float g_z_i[TOTAL];
__device__ __align__(16) float g_v_r[TOTAL];
__device__ __align__(16) float g_v_i[TOTAL];
__device__ __align__(16) float g_g_r[TOTAL];
__device__ __align__(16) float g_g_i[TOTAL];
// bf16 mirrors of MMA inputs (fp32 remains the master state)
__device__ __align__(16) __nv_bfloat16 g_zb_r[TOTAL];
__device__ __align__(16) __nv_bfloat16 g_zb_i[TOTAL];
__device__ __align__(16) __nv_bfloat16 g_vb_r[TOTAL];
__device__ __align__(16) __nv_bfloat16 g_vb_i[TOTAL];
__device__ __align__(16) __nv_bfloat16 g_wb_r[LNN];
__device__ __align__(16) __nv_bfloat16 g_ub_r[LNN];
__device__ __align__(16) __nv_bfloat16 g_wb_i[LNN];
__device__ __align__(16) __nv_bfloat16 g_ub_i[LNN];
__device__ float g_sum_r[NDIM];
__device__ float g_ssq_r[NDIM];
__device__ float g_sum_i[NDIM];
__device__ float g_ssq_i[NDIM];

__device__ __forceinline__ float sigmoidf_(float x) { return 1.f / (1.f + expf(-x)); }

// ---------------- weights -> bf16 (once per run) -----------------------------
__global__ void convert_weights_kernel(const float* __restrict__ Wr,
                                       const float* __restrict__ Ur,
                                       const float* __restrict__ Wi,
                                       const float* __restrict__ Ui) {
    int i = blockIdx.x * blockDim.x + threadIdx.x;
    if (i >= LNN) return;
    g_wb_r[i] = __float2bfloat16(Wr[i]);
    g_ub_r[i] = __float2bfloat16(Ur[i]);
    g_wb_i[i] = __float2bfloat16(Wi[i]);
    g_ub_i[i] = __float2bfloat16(Ui[i]);
}

// ---------------- A^H y : 4 batch rows per block, float4 loads ---------------
__global__ void ahy_kernel(const float* __restrict__ y_r,
                           const float* __restrict__ y_i,
                           const float* __restrict__ A_r,
                           const float* __restrict__ A_i) {
    const int grp = threadIdx.x >> 6;     // 0..3 : batch row within block
    const int t   = threadIdx.x & 63;     // 0..63 : column group (4 cols each)
    const int b   = blockIdx.x * 4 + grp;

    __shared__ float sy_r[4][MDIM];
    __shared__ float sy_i[4][MDIM];
    sy_r[grp][t] = y_r[b * MDIM + t];
    sy_i[grp][t] = y_i[b * MDIM + t];
    __syncthreads();

    const float* Ar = A_r + (size_t)b * MDIM * NDIM + t * 4;
    const float* Ai = A_i + (size_t)b * MDIM * NDIM + t * 4;
    float4 sr = make_float4(0.f, 0.f, 0.f, 0.f);
    float4 si = make_float4(0.f, 0.f, 0.f, 0.f);
#pragma unroll 8
    for (int m = 0; m < MDIM; m++) {
        float4 ar = *(const float4*)&Ar[(size_t)m * NDIM];
        float4 ai = *(const float4*)&Ai[(size_t)m * NDIM];
        float yr = sy_r[grp][m], yi = sy_i[grp][m];
        sr.x += ar.x * yr + ai.x * yi;  si.x += ar.x * yi - ai.x * yr;
        sr.y += ar.y * yr + ai.y * yi;  si.y += ar.y * yi - ai.y * yr;
        sr.z += ar.z * yr + ai.z * yi;  si.z += ar.z * yi - ai.z * yr;
        sr.w += ar.w * yr + ai.w * yi;  si.w += ar.w * yi - ai.w * yr;
    }
    *(float4*)&g_ahy_r[(size_t)b * NDIM + t * 4] = sr;
    *(float4*)&g_ahy_i[(size_t)b * NDIM + t * 4] = si;
}

// ---------------- BatchNorm stats -------------------------------------------
__global__ void zero_stats_kernel() {
    int n = threadIdx.x;
    if (n < NDIM) {
        g_sum_r[n] = 0.f; g_ssq_r[n] = 0.f;
        g_sum_i[n] = 0.f; g_ssq_i[n] = 0.f;
    }
}

// 512 blocks x 32 rows each
__global__ void bn_reduce_kernel() {
    int n = threadIdx.x;
    int r0 = blockIdx.x * 32;
    float sr = 0.f, qr = 0.f, si = 0.f, qi = 0.f;
#pragma unroll 8
    for (int r = 0; r < 32; r++) {
        float vr = g_ahy_r[(size_t)(r0 + r) * NDIM + n];
        float vi = g_ahy_i[(size_t)(r0 + r) * NDIM + n];
        sr += vr; qr += vr * vr;
        si += vi; qi += vi * vi;
    }
    atomicAdd(&g_sum_r[n], sr);
    atomicAdd(&g_ssq_r[n], qr);
    atomicAdd(&g_sum_i[n], si);
    atomicAdd(&g_ssq_i[n], qi);
}

// BN apply + fused analytic layer 0 (z=v=0); also writes bf16 state mirrors
__global__ void bn_apply_layer0_kernel(const float* __restrict__ wdr0,
                                       const float* __restrict__ wdi0,
                                       const float* __restrict__ reta,
                                       const float* __restrict__ br0,
                                       const float* __restrict__ ubr0,
                                       const float* __restrict__ bi0,
                                       const float* __restrict__ ubi0) {
    int idx = blockIdx.x * blockDim.x + threadIdx.x;
    if (idx >= TOTAL) return;
    int n = idx & (NDIM - 1);
    const float invB = 1.f / (float)BATCH;
    float mr = g_sum_r[n] * invB;
    float vr = g_ssq_r[n] * invB - mr * mr;
    float irr = rsqrtf(vr + BN_EPS);
    float mi = g_sum_i[n] * invB;
    float vi2 = g_ssq_i[n] * invB - mi * mi;
    float iri = rsqrtf(vi2 + BN_EPS);
    float ahr = (g_ahy_r[idx] - mr) * irr;
    float ahi = (g_ahy_i[idx] - mi) * iri;
    g_ahy_r[idx] = ahr;
    g_ahy_i[idx] = ahi;

    float re = __ldg(reta);
    float eta = (re > 20.f) ? re : log1pf(expf(re));
    float dr = __ldg(&wdr0[n]) + eta;
    float di = __ldg(&wdi0[n]);
    float inv = 1.f / (dr * dr + di * di);
    float xr = (ahr * dr + ahi * di) * inv;
    float xi = (ahi * dr - ahr * di) * inv;
    float gr = sigmoidf_(__ldg(&br0[n]) + __ldg(&ubr0[n]));
    float gi = sigmoidf_(__ldg(&bi0[n]) + __ldg(&ubi0[n]));
    float znr = gr * xr - gi * xi;
    float zni = gr * xi + gi * xr;
    float vnr = xr - znr, vni = xi - zni;
    g_z_r[idx] = znr; g_z_i[idx] = zni;
    g_v_r[idx] = vnr; g_v_i[idx] = vni;
    g_zb_r[idx] = __float2bfloat16(znr);
    g_zb_i[idx] = __float2bfloat16(zni);
    g_vb_r[idx] = __float2bfloat16(vnr);
    g_vb_i[idx] = __float2bfloat16(vni);
}

// ---------------- bf16 tensor-core gate GEMM (unchanged from R16) -----------
#define GK 32
#define GSTRIDE 40
#define GNIT 16
#define GSTAGES 3
#define GTILE_B (128 * GSTRIDE * 2)
#define GSMEM_BYTES (2 * GSTAGES * GTILE_B)

__device__ __forceinline__ void cp16(unsigned int dst, const void* src) {
    asm volatile("cp.async.cg.shared.global [%0], [%1], 16;" :: "r"(dst), "l"(src));
}
__device__ __forceinline__ void cp_commit() {
    asm volatile("cp.async.commit_group;" ::: "memory");
}
template <int N>
__device__ __forceinline__ void cp_wait() {
    asm volatile("cp.async.wait_group %0;" :: "n"(N) : "memory");
}
__device__ __forceinline__ void ldsm4(unsigned int& r0, unsigned int& r1,
                                      unsigned int& r2, unsigned int& r3,
                                      unsigned int addr) {
    asm volatile("ldmatrix.sync.aligned.m8n8.x4.shared.b16 {%0,%1,%2,%3}, [%4];"
                 : "=r"(r0), "=r"(r1), "=r"(r2), "=r"(r3) : "r"(addr));
}
__device__ __forceinline__ void mma_bf16(float* c, const unsigned int* a,
                                         const unsigned int* b) {
    asm volatile(
        "mma.sync.aligned.m16n8k16.row.col.f32.bf16.bf16.f32 "
        "{%0,%1,%2,%3},{%4,%5,%6,%7},{%8,%9},{%0,%1,%2,%3};"
        : "+f"(c[0]), "+f"(c[1]), "+f"(c[2]), "+f"(c[3])
        : "r"(a[0]), "r"(a[1]), "r"(a[2]), "r"(a[3]), "r"(b[0]), "r"(b[1]));
}

__global__ __launch_bounds__(256, 2)
void gate_gemm_bf16(int layer,
                    const float* __restrict__ br, const float* __restrict__ ubr,
                    const float* __restrict__ bi, const float* __restrict__ ubi) {
    const size_t wo = (size_t)layer * NDIM * NDIM;
    const __nv_bfloat16* Z = blockIdx.z ? g_zb_i : g_zb_r;
    const __nv_bfloat16* V = blockIdx.z ? g_vb_i : g_vb_r;
    const __nv_bfloat16* W = (blockIdx.z ? g_wb_i : g_wb_r) + wo;
    const __nv_bfloat16* U = (blockIdx.z ? g_ub_i : g_ub_r) + wo;
    const float* B1 = blockIdx.z ? bi : br;
    const float* B2 = blockIdx.z ? ubi : ubr;
    float* G        = blockIdx.z ? g_g_i : g_g_r;

    extern __shared__ __nv_bfloat16 smb16[];
    __nv_bfloat16* As = smb16;
    __nv_bfloat16* Bs = smb16 + GSTAGES * 128 * GSTRIDE;

    const int tid  = threadIdx.x;
    const int row0 = blockIdx.y * 128;
    const int col0 = blockIdx.x * 128;
    const int wid  = tid >> 5, lane = tid & 31;
    const int wm = wid >> 2;
    const int wn = wid & 3;
    const int grp = lane >> 2, tig = lane & 3;

    const int rselA = (lane & 7) + ((lane >> 3) & 1) * 8;
    const int kbA   = (lane >> 4) * 16;
    const int cselB = (lane & 7) + (lane >> 4) * 8;
    const int kbB   = ((lane >> 3) & 1) * 16;

    const int lrow = tid >> 1;
    const int lkc  = (tid & 1) * 16;

    float acc[4][4][4];
#pragma unroll
    for (int a = 0; a < 4; a++)
#pragma unroll
        for (int b = 0; b < 4; b++)
#pragma unroll
            for (int c = 0; c < 4; c++) acc[a][b][c] = 0.f;

    unsigned int asb = (unsigned int)__cvta_generic_to_shared(As);
    unsigned int bsb = (unsigned int)__cvta_generic_to_shared(Bs);

    auto load_tile = [&](int it, int buf) {
        int kg = it * GK;
        const __nv_bfloat16* a_src = (kg < 256) ? Z : V;
        const __nv_bfloat16* b_src = (kg < 256) ? W : U;
        int kk = kg & 255;
        unsigned int ab = asb + (unsigned int)(buf * GTILE_B);
        unsigned int bb = bsb + (unsigned int)(buf * GTILE_B);
        unsigned int so = (unsigned int)((lrow * GSTRIDE + lkc) * 2);
        const __nv_bfloat16* ag = a_src + (size_t)(row0 + lrow) * NDIM + kk + lkc;
        const __nv_bfloat16* bg = b_src + (size_t)(col0 + lrow) * NDIM + kk + lkc;
        cp16(ab + so,      ag);
        cp16(ab + so + 16, ag + 8);
        cp16(bb + so,      bg);
        cp16(bb + so + 16, bg + 8);
        cp_commit();
    };

    load_tile(0, 0);
    load_tile(1, 1);

    int buf = 0;
    for (int i = 0; i < GNIT; i++) {
        cp_wait<1>();
        __syncthreads();

        unsigned int aB = asb + (unsigned int)(buf * GTILE_B);
        unsigned int bB = bsb + (unsigned int)(buf * GTILE_B);
#pragma unroll
        for (int ks = 0; ks < 2; ks++) {
            int kb = ks * 16;
            unsigned int af[4][4], bf[4][2];
#pragma unroll
            for (int mt = 0; mt < 4; mt++) {
                unsigned int ad = aB + (unsigned int)(((wm * 64 + mt * 16 + rselA) * GSTRIDE
                                                      + kb) * 2 + kbA);
                ldsm4(af[mt][0], af[mt][1], af[mt][2], af[mt][3], ad);
            }
#pragma unroll
            for (int np = 0; np < 2; np++) {
                unsigned int bd = bB + (unsigned int)(((wn * 32 + np * 16 + cselB) * GSTRIDE
                                                      + kb) * 2 + kbB);
                ldsm4(bf[2 * np][0], bf[2 * np][1], bf[2 * np + 1][0], bf[2 * np + 1][1], bd);
            }
#pragma unroll
            for (int mt = 0; mt < 4; mt++)
#pragma unroll
                for (int nt = 0; nt < 4; nt++)
                    mma_bf16(acc[mt][nt], af[mt], bf[nt]);
        }

        if (i + 2 < GNIT) load_tile(i + 2, (i + 2) % GSTAGES);
        buf = (buf + 1) % GSTAGES;
    }

#pragma unroll
    for (int nt = 0; nt < 4; nt++) {
        int c = col0 + wn * 32 + nt * 8 + tig * 2;
        float bv0 = __ldg(&B1[c]) + __ldg(&B2[c]);
        float bv1 = __ldg(&B1[c + 1]) + __ldg(&B2[c + 1]);
#pragma unroll
        for (int mt = 0; mt < 4; mt++) {
            int r = row0 + wm * 64 + mt * 16 + grp;
            float2 lo, hi;
            lo.x = sigmoidf_(acc[mt][nt][0] + bv0);
            lo.y = sigmoidf_(acc[mt][nt][1] + bv1);
            hi.x = sigmoidf_(acc[mt][nt][2] + bv0);
            hi.y = sigmoidf_(acc[mt][nt][3] + bv1);
            *(float2*)&G[(size_t)r * NDIM + c]       = lo;
            *(float2*)&G[(size_t)(r + 8) * NDIM + c] = hi;
        }
    }
}

// ---------------- fused elementwise layer update -----------------------------
// last==0: write next z/v state (+bf16 mirrors).
// last==1: apply amplitude mask and write final output directly; skip state.
__global__ void update_kernel(const float* __restrict__ w_r,
                              const float* __restrict__ w_i,
                              const float* __restrict__ raw_eta_l,
                              int last,
                              float* __restrict__ out, long long max_floats,
                              const float* thr, const float* alpha, int use_ptrs) {
    int idx = blockIdx.x * blockDim.x + threadIdx.x;
    if (idx >= TOTAL) return;
    int n = idx & (NDIM - 1);
    float reta = __ldg(raw_eta_l);
    float eta = (reta > 20.f) ? reta : log1pf(expf(reta));
    float dr = __ldg(&w_r[n]) + eta;
    float di = __ldg(&w_i[n]);
    float inv = 1.f / (dr * dr + di * di);

    float ahr = g_ahy_r[idx], ahi = g_ahy_i[idx];
    float zr = g_z_r[idx], zi = g_z_i[idx];
    float vr = g_v_r[idx], vi = g_v_i[idx];

    float nr = ahr + eta * (zr - vr);
    float ni = ahi + eta * (zi - vi);
    float xr = (nr * dr + ni * di) * inv;
    float xi = (ni * dr - nr * di) * inv;
    float ur = xr + vr, ui = xi + vi;

    float gr = g_g_r[idx], gi = g_g_i[idx];
    float znr = gr * ur - gi * ui + (1.f - gr) * zr + gi * zi;
    float zni = gr * ui + gi * ur + (1.f - gr) * zi - gi * zr;

    if (last) {
        float amp = sqrtf(znr * znr + zni * zni);
        float t = use_ptrs ? __ldg(thr) : 0.1f;
        float a = use_ptrs ? __ldg(alpha) : 2.0f;
        float m = 1.f / (1.f + expf(-a * (amp - t)));
        if (idx < max_floats) out[idx] = znr * m;
        long long o = (long long)idx + TOTAL;
        if (o < max_floats) out[o] = zni * m;
    } else {
        float vnr = vr + xr - znr;
        float vni = vi + xi - zni;
        g_z_r[idx] = znr; g_z_i[idx] = zni;
        g_v_r[idx] = vnr; g_v_i[idx] = vni;
        g_zb_r[idx] = __float2bfloat16(znr);
        g_zb_i[idx] = __float2bfloat16(zni);
        g_vb_r[idx] = __float2bfloat16(vnr);
        g_vb_i[idx] = __float2bfloat16(vni);
    }
}

// ---------------- launch ----------------------------------------------------
extern "C" void kernel_launch(void* const* d_in, const int* in_sizes, int n_in,
                              void* d_out, int out_size) {
    static const long long sig[17] = {SZ_BM, SZ_BM, SZ_BMN, SZ_BMN, SZ_LN, SZ_LN, SZ_L,
                                      SZ_LNN, SZ_LN, SZ_LNN, SZ_LN, SZ_LNN, SZ_LN,
                                      SZ_LNN, SZ_LN, 1, 1};
    static const long long srt[17] = {SZ_BMN, SZ_BMN, SZ_LN, SZ_LNN, SZ_LN, SZ_LNN,
                                      SZ_LN, SZ_LNN, SZ_LN, SZ_LNN, 1, SZ_L, 1,
                                      SZ_LN, SZ_LN, SZ_BM, SZ_BM};

    int map[17];
    int have_scalars = 0;
    int matched = 0;

    if (n_in == 17 || n_in == 15) {
        int ok = 1;
        for (int i = 0; i < n_in; i++)
            if ((long long)in_sizes[i] != sig[i]) { ok = 0; break; }
        if (ok) {
            for (int i = 0; i < 17; i++) map[i] = i;
            have_scalars = (n_in == 17);
            matched = 1;
        }
    }
    if (!matched && n_in == 17) {
        int ok = 1;
        for (int i = 0; i < 17; i++)
            if ((long long)in_sizes[i] != srt[i]) { ok = 0; break; }
        if (ok) {
            map[3] = 0;  map[2] = 1;  map[14] = 2; map[13] = 3; map[10] = 4;
            map[9] = 5;  map[12] = 6; map[11] = 7; map[8] = 8;  map[7] = 9;
            map[16] = 10; map[6] = 11; map[15] = 12; map[5] = 13; map[4] = 14;
            map[1] = 15; map[0] = 16;
            have_scalars = 1;
            matched = 2;
        }
    }
    if (!matched && n_in == 17) {
        int ok = 1;
        for (int i = 0; i < 17; i++)
            if ((long long)in_sizes[i] != sig[16 - i]) { ok = 0; break; }
        if (ok) {
            for (int i = 0; i < 17; i++) map[i] = 16 - i;
            have_scalars = 1;
            matched = 3;
        }
    }

    if (!matched) return;

    const float* y_r   = (const float*)d_in[map[0]];
    const float* y_i   = (const float*)d_in[map[1]];
    const float* A_r   = (const float*)d_in[map[2]];
    const float* A_i   = (const float*)d_in[map[3]];
    const float* wdr   = (const float*)d_in[map[4]];
    const float* wdi   = (const float*)d_in[map[5]];
    const float* reta  = (const float*)d_in[map[6]];
    const float* Wr    = (const float*)d_in[map[7]];
    const float* br    = (const float*)d_in[map[8]];
    const float* Ur    = (const float*)d_in[map[9]];
    const float* ubr   = (const float*)d_in[map[10]];
    const float* Wi    = (const float*)d_in[map[11]];
    const float* bi    = (const float*)d_in[map[12]];
    const float* Ui    = (const float*)d_in[map[13]];
    const float* ubi   = (const float*)d_in[map[14]];
    const float* thr   = have_scalars ? (const float*)d_in[map[15]] : (const float*)0;
    const float* alpha = have_scalars ? (const float*)d_in[map[16]] : (const float*)0;

    const int EW_BLOCKS = TOTAL / 256;

    cudaFuncSetAttribute(gate_gemm_bf16,
                         cudaFuncAttributeMaxDynamicSharedMemorySize, GSMEM_BYTES);

    convert_weights_kernel<<<(LNN + 255) / 256, 256>>>(Wr, Ur, Wi, Ui);
    zero_stats_kernel<<<1, 256>>>();
    ahy_kernel<<<BATCH / 4, 256>>>(y_r, y_i, A_r, A_i);
    bn_reduce_kernel<<<BATCH / 32, 256>>>();
    bn_apply_layer0_kernel<<<EW_BLOCKS, 256>>>(wdr, wdi, reta, br, ubr, bi, ubi);

    for (int l = 1; l < L_LAYERS; l++) {
        size_t bo = (size_t)l * NDIM;
        int last = (l == L_LAYERS - 1);
        dim3 grid(NDIM / 128, BATCH / 128, 2);
        gate_gemm_bf16<<<grid, 256, GSMEM_BYTES>>>(l, br + bo, ubr + bo,
                                                   bi + bo, ubi + bo);
        update_kernel<<<EW_BLOCKS, 256>>>(wdr + bo, wdi + bo, reta + l, last,
                                          (float*)d_out, (long long)out_size,
                                          thr, alpha, have_scalars);
    }
}